// round 1
// baseline (speedup 1.0000x reference)
#include <cuda_runtime.h>
#include <math.h>

// Problem constants (fixed by the reference)
#define B_  4
#define S_  2048
#define H_  16
#define D_  64
#define BQ  64     // query rows per block
#define BK  64     // key cols per tile
#define PAD 68     // smem row stride in floats (16B-aligned, de-conflicted)

// Flash-attention, fp32 CUDA cores.
// Grid: (S/BQ, H, B). Block: 256 threads = 16x16 (ty, tx).
// Each thread owns 4 query rows (r = ty + 16*i, strided) and:
//   - 4 score cols (c = tx + 16*j, strided)  -> mask loads coalesced over tx
//   - 4 output dims (d = 4*tx + j, blocked)  -> float4 V loads + float4 O stores
__global__ __launch_bounds__(256, 2)
void attn_fp32_kernel(const float* __restrict__ q,
                      const float* __restrict__ k,
                      const float* __restrict__ v,
                      const int*   __restrict__ mask,
                      float* __restrict__ out)
{
    extern __shared__ float smem[];
    float* Qs = smem;              // [BQ][PAD]
    float* Ks = Qs + BQ * PAD;     // [BK][PAD]
    float* Vs = Ks + BK * PAD;     // [BK][PAD]
    float* Ps = Vs + BK * PAD;     // [BQ][PAD]

    const int tid = threadIdx.x;
    const int tx  = tid & 15;
    const int ty  = tid >> 4;
    const int qt  = blockIdx.x;
    const int h   = blockIdx.y;
    const int b   = blockIdx.z;
    const int q0  = qt * BQ;

    // ---- load Q tile (64 x 64 floats) via float4, fully coalesced ----
    const float* qb = q + (((size_t)b * S_ + q0) * H_ + h) * D_;
    #pragma unroll
    for (int it = 0; it < 4; it++) {
        int idx = tid + it * 256;
        int r   = idx >> 4;        // 0..63
        int c4  = idx & 15;        // float4 index 0..15
        float4 val = *(const float4*)(qb + (size_t)r * (H_ * D_) + c4 * 4);
        *(float4*)(Qs + r * PAD + c4 * 4) = val;
    }

    float m_i[4], l_i[4], o[4][4];
    #pragma unroll
    for (int i = 0; i < 4; i++) {
        m_i[i] = -INFINITY;
        l_i[i] = 0.f;
        #pragma unroll
        for (int j = 0; j < 4; j++) o[i][j] = 0.f;
    }

    const int* mb = mask + (((size_t)b * H_ + h) * S_ + q0) * S_;

    for (int kt = 0; kt < S_ / BK; kt++) {
        const int k0 = kt * BK;

        __syncthreads();  // previous PV / QK reads done before overwrite

        // ---- load K, V tiles ----
        const float* kb = k + (((size_t)b * S_ + k0) * H_ + h) * D_;
        const float* vb = v + (((size_t)b * S_ + k0) * H_ + h) * D_;
        #pragma unroll
        for (int it = 0; it < 4; it++) {
            int idx = tid + it * 256;
            int r   = idx >> 4;
            int c4  = idx & 15;
            *(float4*)(Ks + r * PAD + c4 * 4) =
                *(const float4*)(kb + (size_t)r * (H_ * D_) + c4 * 4);
            *(float4*)(Vs + r * PAD + c4 * 4) =
                *(const float4*)(vb + (size_t)r * (H_ * D_) + c4 * 4);
        }

        // ---- prefetch mask tile into registers (hidden under QK compute) ----
        int mv[4][4];
        #pragma unroll
        for (int i = 0; i < 4; i++) {
            const int* mrow = mb + (size_t)(ty + 16 * i) * S_ + k0 + tx;
            #pragma unroll
            for (int j = 0; j < 4; j++)
                mv[i][j] = mrow[16 * j];
        }

        __syncthreads();  // K/V tiles visible

        // ---- S = Q @ K^T (register-tiled 4x4, float4 over d) ----
        float s[4][4];
        #pragma unroll
        for (int i = 0; i < 4; i++)
            #pragma unroll
            for (int j = 0; j < 4; j++) s[i][j] = 0.f;

        #pragma unroll
        for (int d4 = 0; d4 < 16; d4++) {
            float4 a[4], bb[4];
            #pragma unroll
            for (int i = 0; i < 4; i++)
                a[i] = *(const float4*)(Qs + (ty + 16 * i) * PAD + d4 * 4);
            #pragma unroll
            for (int j = 0; j < 4; j++)
                bb[j] = *(const float4*)(Ks + (tx + 16 * j) * PAD + d4 * 4);
            #pragma unroll
            for (int i = 0; i < 4; i++) {
                #pragma unroll
                for (int j = 0; j < 4; j++) {
                    s[i][j] = fmaf(a[i].x, bb[j].x, s[i][j]);
                    s[i][j] = fmaf(a[i].y, bb[j].y, s[i][j]);
                    s[i][j] = fmaf(a[i].z, bb[j].z, s[i][j]);
                    s[i][j] = fmaf(a[i].w, bb[j].w, s[i][j]);
                }
            }
        }

        // ---- mask (faithful: value 1e-20, NOT -inf), online softmax ----
        #pragma unroll
        for (int i = 0; i < 4; i++) {
            #pragma unroll
            for (int j = 0; j < 4; j++)
                s[i][j] = mv[i][j] ? s[i][j] * 0.125f : 1e-20f;

            float mx = fmaxf(fmaxf(s[i][0], s[i][1]), fmaxf(s[i][2], s[i][3]));
            #pragma unroll
            for (int off = 8; off > 0; off >>= 1)
                mx = fmaxf(mx, __shfl_xor_sync(0xffffffffu, mx, off));

            float mnew  = fmaxf(m_i[i], mx);
            float alpha = __expf(m_i[i] - mnew);  // exp(-inf)=0 on first tile

            float rs = 0.f;
            #pragma unroll
            for (int j = 0; j < 4; j++) {
                float p = __expf(s[i][j] - mnew);
                s[i][j] = p;
                rs += p;
            }
            #pragma unroll
            for (int off = 8; off > 0; off >>= 1)
                rs += __shfl_xor_sync(0xffffffffu, rs, off);

            l_i[i] = l_i[i] * alpha + rs;
            m_i[i] = mnew;
            #pragma unroll
            for (int j = 0; j < 4; j++) o[i][j] *= alpha;

            // stash P for the PV GEMM (strided cols -> conflict-free stores)
            #pragma unroll
            for (int j = 0; j < 4; j++)
                Ps[(ty + 16 * i) * PAD + tx + 16 * j] = s[i][j];
        }

        __syncthreads();  // P visible to all

        // ---- O += P @ V (register-tiled, float4 over k and over dcol) ----
        #pragma unroll
        for (int k4 = 0; k4 < 16; k4++) {
            float4 pr[4];
            #pragma unroll
            for (int i = 0; i < 4; i++)
                pr[i] = *(const float4*)(Ps + (ty + 16 * i) * PAD + k4 * 4);
            float4 vv[4];
            #pragma unroll
            for (int e = 0; e < 4; e++)
                vv[e] = *(const float4*)(Vs + (k4 * 4 + e) * PAD + 4 * tx);
            #pragma unroll
            for (int i = 0; i < 4; i++) {
                float p0 = pr[i].x, p1 = pr[i].y, p2 = pr[i].z, p3 = pr[i].w;
                o[i][0] = fmaf(p0, vv[0].x, o[i][0]);
                o[i][1] = fmaf(p0, vv[0].y, o[i][1]);
                o[i][2] = fmaf(p0, vv[0].z, o[i][2]);
                o[i][3] = fmaf(p0, vv[0].w, o[i][3]);
                o[i][0] = fmaf(p1, vv[1].x, o[i][0]);
                o[i][1] = fmaf(p1, vv[1].y, o[i][1]);
                o[i][2] = fmaf(p1, vv[1].z, o[i][2]);
                o[i][3] = fmaf(p1, vv[1].w, o[i][3]);
                o[i][0] = fmaf(p2, vv[2].x, o[i][0]);
                o[i][1] = fmaf(p2, vv[2].y, o[i][1]);
                o[i][2] = fmaf(p2, vv[2].z, o[i][2]);
                o[i][3] = fmaf(p2, vv[2].w, o[i][3]);
                o[i][0] = fmaf(p3, vv[3].x, o[i][0]);
                o[i][1] = fmaf(p3, vv[3].y, o[i][1]);
                o[i][2] = fmaf(p3, vv[3].z, o[i][2]);
                o[i][3] = fmaf(p3, vv[3].w, o[i][3]);
            }
        }
    }

    // ---- epilogue: normalize and store (float4, coalesced over tx) ----
    #pragma unroll
    for (int i = 0; i < 4; i++) {
        float inv = 1.0f / l_i[i];
        float4 res;
        res.x = o[i][0] * inv;
        res.y = o[i][1] * inv;
        res.z = o[i][2] * inv;
        res.w = o[i][3] * inv;
        float* ob = out + (((size_t)b * S_ + q0 + ty + 16 * i) * H_ + h) * D_ + 4 * tx;
        *(float4*)ob = res;
    }
}

extern "C" void kernel_launch(void* const* d_in, const int* in_sizes, int n_in,
                              void* d_out, int out_size)
{
    const float* q    = (const float*)d_in[0];
    const float* k    = (const float*)d_in[1];
    const float* v    = (const float*)d_in[2];
    const int*   mask = (const int*)d_in[3];
    float*       out  = (float*)d_out;

    const int smem_bytes = (BQ + 3 * BK) * PAD * (int)sizeof(float);  // 69632 B
    cudaFuncSetAttribute(attn_fp32_kernel,
                         cudaFuncAttributeMaxDynamicSharedMemorySize, smem_bytes);

    dim3 grid(S_ / BQ, H_, B_);
    attn_fp32_kernel<<<grid, 256, smem_bytes>>>(q, k, v, mask, out);
}

// round 3
// speedup vs baseline: 1.7792x; 1.7792x over previous
#include <cuda_runtime.h>
#include <cuda_bf16.h>
#include <cstdint>
#include <math.h>

#define B_ 4
#define S_ 2048
#define H_ 16
#define D_ 64
#define BQ 128
#define BK 64
#define NTILE (S_/BK)            // 32
#define NELEM (B_*H_*S_*D_)      // 8388608
#define N4 (NELEM/4)             // 2097152

// Pre-converted bf16 hi/lo operands, head-major [b][h][s][d]
__device__ __nv_bfloat16 g_Qhi[NELEM];
__device__ __nv_bfloat16 g_Qlo[NELEM];
__device__ __nv_bfloat16 g_Khi[NELEM];
__device__ __nv_bfloat16 g_Klo[NELEM];
__device__ __nv_bfloat16 g_Vhi[NELEM];
__device__ __nv_bfloat16 g_Vlo[NELEM];

// ---------------- conversion / layout pre-pass ----------------
__global__ void cvt_kernel(const float4* __restrict__ q,
                           const float4* __restrict__ k,
                           const float4* __restrict__ v)
{
    int j = blockIdx.x * blockDim.x + threadIdx.x;
    if (j >= 3 * N4) return;
    int tsel = j / N4;
    int i = j - tsel * N4;

    const float4*  src = (tsel == 0) ? q : (tsel == 1) ? k : v;
    __nv_bfloat16* dh  = (tsel == 0) ? g_Qhi : (tsel == 1) ? g_Khi : g_Vhi;
    __nv_bfloat16* dl  = (tsel == 0) ? g_Qlo : (tsel == 1) ? g_Klo : g_Vlo;
    const float scale  = (tsel == 0) ? 0.125f : 1.0f;

    // src linear float4 index i over [b][s][h][c4]
    int c4 = i & 15, h = (i >> 4) & 15, s = (i >> 8) & 2047, b = i >> 19;
    float4 x = src[i];
    x.x *= scale; x.y *= scale; x.z *= scale; x.w *= scale;

    __nv_bfloat162 h01 = __floats2bfloat162_rn(x.x, x.y);
    __nv_bfloat162 h23 = __floats2bfloat162_rn(x.z, x.w);
    __nv_bfloat162 l01 = __floats2bfloat162_rn(x.x - __bfloat162float(h01.x),
                                               x.y - __bfloat162float(h01.y));
    __nv_bfloat162 l23 = __floats2bfloat162_rn(x.z - __bfloat162float(h23.x),
                                               x.w - __bfloat162float(h23.y));

    size_t p = ((size_t)(b * 16 + h) * 2048 + s) * 64 + c4 * 4;
    *(__nv_bfloat162*)(dh + p)     = h01;
    *(__nv_bfloat162*)(dh + p + 2) = h23;
    *(__nv_bfloat162*)(dl + p)     = l01;
    *(__nv_bfloat162*)(dl + p + 2) = l23;
}

// ---------------- mma / ldmatrix / cp.async primitives ----------------
__device__ __forceinline__ void hmma(float* c, const uint32_t* a, uint32_t b0, uint32_t b1){
    asm("mma.sync.aligned.m16n8k16.row.col.f32.bf16.bf16.f32 "
        "{%0,%1,%2,%3}, {%4,%5,%6,%7}, {%8,%9}, {%0,%1,%2,%3};"
        : "+f"(c[0]), "+f"(c[1]), "+f"(c[2]), "+f"(c[3])
        : "r"(a[0]), "r"(a[1]), "r"(a[2]), "r"(a[3]), "r"(b0), "r"(b1));
}
__device__ __forceinline__ void ldsm4(uint32_t* r, uint32_t a){
    asm volatile("ldmatrix.sync.aligned.m8n8.x4.shared.b16 {%0,%1,%2,%3}, [%4];"
        : "=r"(r[0]), "=r"(r[1]), "=r"(r[2]), "=r"(r[3]) : "r"(a));
}
__device__ __forceinline__ void ldsm4t(uint32_t* r, uint32_t a){
    asm volatile("ldmatrix.sync.aligned.m8n8.x4.trans.shared.b16 {%0,%1,%2,%3}, [%4];"
        : "=r"(r[0]), "=r"(r[1]), "=r"(r[2]), "=r"(r[3]) : "r"(a));
}
__device__ __forceinline__ void cp16(uint32_t dst, const void* src){
    asm volatile("cp.async.cg.shared.global [%0], [%1], 16;" :: "r"(dst), "l"(src));
}
__device__ __forceinline__ void cp_commit(){ asm volatile("cp.async.commit_group;"); }
template<int N> __device__ __forceinline__ void cp_wait(){
    asm volatile("cp.async.wait_group %0;" :: "n"(N));
}
__device__ __forceinline__ uint32_t smem_u32(const void* p){
    uint32_t a;
    asm("{ .reg .u64 t; cvta.to.shared.u64 t, %1; cvt.u32.u64 %0, t; }" : "=r"(a) : "l"(p));
    return a;
}
__device__ __forceinline__ void split2(float x, float y, uint32_t& hi, uint32_t& lo){
    __nv_bfloat162 h = __floats2bfloat162_rn(x, y);
    __nv_bfloat162 l = __floats2bfloat162_rn(x - __bfloat162float(h.x),
                                             y - __bfloat162float(h.y));
    hi = *(uint32_t*)&h; lo = *(uint32_t*)&l;
}

// smem: 2 stages x 4 tiles (Khi,Klo,Vhi,Vlo), each 64 rows x 144B (72 bf16, pad 8)
#define TILEB   9216
#define STAGEB  36864
#define SMEMB   (2*STAGEB)   // 73728

__device__ __forceinline__ void issue_tile(uint32_t smbase, int st,
    const __nv_bfloat16* Kh, const __nv_bfloat16* Kl,
    const __nv_bfloat16* Vh, const __nv_bfloat16* Vl, int k0, int tid)
{
    const char* srcs[4] = {
        (const char*)(Kh + (size_t)k0 * 64), (const char*)(Kl + (size_t)k0 * 64),
        (const char*)(Vh + (size_t)k0 * 64), (const char*)(Vl + (size_t)k0 * 64) };
    uint32_t dst0 = smbase + st * STAGEB;
    #pragma unroll
    for (int i = 0; i < 8; i++){
        int sub = i >> 1;
        int c   = ((i & 1) << 8) + tid;   // 0..511 chunk within sub-tile
        int r   = c >> 3, o = c & 7;
        cp16(dst0 + sub * TILEB + r * 144 + o * 16, srcs[sub] + r * 128 + o * 16);
    }
    cp_commit();
}

// ---------------- main flash-attention kernel ----------------
__global__ __launch_bounds__(256)
void attn_hmma_kernel(const int* __restrict__ mask, float* __restrict__ out)
{
    extern __shared__ char smc[];
    const uint32_t smbase = smem_u32(smc);
    const int tid = threadIdx.x;
    const int w = tid >> 5, lane = tid & 31;
    const int g = lane >> 2, t = lane & 3;
    const int qt = blockIdx.x, h = blockIdx.y, b = blockIdx.z;
    const int bh = b * H_ + h;
    const int q0 = qt * BQ;
    const int qrow0 = q0 + w * 16;

    const __nv_bfloat16* Kh = g_Khi + (size_t)bh * S_ * 64;
    const __nv_bfloat16* Kl = g_Klo + (size_t)bh * S_ * 64;
    const __nv_bfloat16* Vh = g_Vhi + (size_t)bh * S_ * 64;
    const __nv_bfloat16* Vl = g_Vlo + (size_t)bh * S_ * 64;

    // ---- Q fragments from gmem (one-time): aQ[kc][0..3] ----
    uint32_t aQh[4][4], aQl[4][4];
    {
        const __nv_bfloat16* Qh = g_Qhi + ((size_t)bh * S_ + qrow0) * 64;
        const __nv_bfloat16* Ql = g_Qlo + ((size_t)bh * S_ + qrow0) * 64;
        #pragma unroll
        for (int kc = 0; kc < 4; kc++){
            int c0 = kc * 16 + 2 * t;
            aQh[kc][0] = *(const uint32_t*)(Qh + g * 64 + c0);
            aQh[kc][1] = *(const uint32_t*)(Qh + (g + 8) * 64 + c0);
            aQh[kc][2] = *(const uint32_t*)(Qh + g * 64 + c0 + 8);
            aQh[kc][3] = *(const uint32_t*)(Qh + (g + 8) * 64 + c0 + 8);
            aQl[kc][0] = *(const uint32_t*)(Ql + g * 64 + c0);
            aQl[kc][1] = *(const uint32_t*)(Ql + (g + 8) * 64 + c0);
            aQl[kc][2] = *(const uint32_t*)(Ql + g * 64 + c0 + 8);
            aQl[kc][3] = *(const uint32_t*)(Ql + (g + 8) * 64 + c0 + 8);
        }
    }

    const int* mr0 = mask + ((size_t)bh * S_ + qrow0 + g) * S_;
    const int* mr8 = mr0 + 8 * S_;

    float o[8][4];
    #pragma unroll
    for (int i = 0; i < 8; i++)
        #pragma unroll
        for (int j = 0; j < 4; j++) o[i][j] = 0.f;
    float lsum0 = 0.f, lsum1 = 0.f;

    // ldmatrix lane address components
    const int krow_l = (lane & 7) + ((lane >> 4) << 3);
    const uint32_t kcol_l = ((lane >> 3) & 1) * 16;
    const int vrow_l = (lane & 7) + (((lane >> 3) & 1) << 3);
    const uint32_t vcol_l = (lane >> 4) * 16;

    issue_tile(smbase, 0, Kh, Kl, Vh, Vl, 0, tid);

    for (int tt = 0; tt < NTILE; tt++){
        const int k0 = tt * BK;
        const int st = tt & 1;
        if (tt + 1 < NTILE){
            issue_tile(smbase, (tt + 1) & 1, Kh, Kl, Vh, Vl, k0 + BK, tid);
            cp_wait<1>();
        } else {
            cp_wait<0>();
        }
        __syncthreads();

        const uint32_t kbh = smbase + st * STAGEB;
        const uint32_t kbl = kbh + TILEB;
        const uint32_t vbh = kbh + 2 * TILEB;
        const uint32_t vbl = kbh + 3 * TILEB;

        // one-chunk-ahead mask prefetch
        int2 mcur[4], mnxt[4];
        {
            int cb = k0 + 2 * t;
            mcur[0] = *(const int2*)(mr0 + cb);
            mcur[1] = *(const int2*)(mr8 + cb);
            mcur[2] = *(const int2*)(mr0 + cb + 8);
            mcur[3] = *(const int2*)(mr8 + cb + 8);
        }

        #pragma unroll
        for (int c = 0; c < 4; c++){
            if (c < 3){
                int cb = k0 + (c + 1) * 16 + 2 * t;
                mnxt[0] = *(const int2*)(mr0 + cb);
                mnxt[1] = *(const int2*)(mr8 + cb);
                mnxt[2] = *(const int2*)(mr0 + cb + 8);
                mnxt[3] = *(const int2*)(mr8 + cb + 8);
            }

            // ---- QK: sc0 (keys c*16+0..7), sc1 (keys c*16+8..15) ----
            float sc0[4] = {0.f, 0.f, 0.f, 0.f};
            float sc1[4] = {0.f, 0.f, 0.f, 0.f};
            const uint32_t ka_h = kbh + (uint32_t)(c * 16 + krow_l) * 144 + kcol_l;
            const uint32_t ka_l = kbl + (uint32_t)(c * 16 + krow_l) * 144 + kcol_l;
            #pragma unroll
            for (int kc = 0; kc < 4; kc++){
                uint32_t bhf[4], blf[4];
                ldsm4(bhf, ka_h + kc * 32);
                ldsm4(blf, ka_l + kc * 32);
                hmma(sc0, aQh[kc], bhf[0], bhf[1]);
                hmma(sc1, aQh[kc], bhf[2], bhf[3]);
                hmma(sc0, aQh[kc], blf[0], blf[1]);
                hmma(sc1, aQh[kc], blf[2], blf[3]);
                hmma(sc0, aQl[kc], bhf[0], bhf[1]);
                hmma(sc1, aQl[kc], bhf[2], bhf[3]);
            }

            // ---- mask + exp (masked -> p = 1.0, faithful to exp(1e-20)) ----
            float p00 = mcur[0].x ? __expf(sc0[0]) : 1.f;
            float p01 = mcur[0].y ? __expf(sc0[1]) : 1.f;
            float p02 = mcur[1].x ? __expf(sc0[2]) : 1.f;
            float p03 = mcur[1].y ? __expf(sc0[3]) : 1.f;
            float p10 = mcur[2].x ? __expf(sc1[0]) : 1.f;
            float p11 = mcur[2].y ? __expf(sc1[1]) : 1.f;
            float p12 = mcur[3].x ? __expf(sc1[2]) : 1.f;
            float p13 = mcur[3].y ? __expf(sc1[3]) : 1.f;
            lsum0 += (p00 + p01) + (p10 + p11);
            lsum1 += (p02 + p03) + (p12 + p13);

            // ---- P -> A-fragments (hi/lo) ----
            uint32_t ph[4], pl[4];
            split2(p00, p01, ph[0], pl[0]);
            split2(p02, p03, ph[1], pl[1]);
            split2(p10, p11, ph[2], pl[2]);
            split2(p12, p13, ph[3], pl[3]);

            // ---- PV: O += Ph@Vh + Ph@Vl + Pl@Vh ----
            const uint32_t va_h = vbh + (uint32_t)(c * 16 + vrow_l) * 144 + vcol_l;
            const uint32_t va_l = vbl + (uint32_t)(c * 16 + vrow_l) * 144 + vcol_l;
            #pragma unroll
            for (int dt2 = 0; dt2 < 4; dt2++){
                uint32_t bhf[4], blf[4];
                ldsm4t(bhf, va_h + dt2 * 32);
                ldsm4t(blf, va_l + dt2 * 32);
                hmma(o[2 * dt2],     ph, bhf[0], bhf[1]);
                hmma(o[2 * dt2 + 1], ph, bhf[2], bhf[3]);
                hmma(o[2 * dt2],     ph, blf[0], blf[1]);
                hmma(o[2 * dt2 + 1], ph, blf[2], blf[3]);
                hmma(o[2 * dt2],     pl, bhf[0], bhf[1]);
                hmma(o[2 * dt2 + 1], pl, bhf[2], bhf[3]);
            }

            if (c < 3){
                #pragma unroll
                for (int i = 0; i < 4; i++) mcur[i] = mnxt[i];
            }
        }
        __syncthreads();
    }

    // ---- row-sum reduce over the 4 lanes of each row group ----
    lsum0 += __shfl_xor_sync(0xffffffffu, lsum0, 1);
    lsum0 += __shfl_xor_sync(0xffffffffu, lsum0, 2);
    lsum1 += __shfl_xor_sync(0xffffffffu, lsum1, 1);
    lsum1 += __shfl_xor_sync(0xffffffffu, lsum1, 2);
    const float inv0 = 1.0f / lsum0;
    const float inv1 = 1.0f / lsum1;

    // ---- store O: out[b][q][h][d] ----
    float* o0 = out + (((size_t)b * S_ + qrow0 + g) * H_ + h) * D_;
    float* o8 = out + (((size_t)b * S_ + qrow0 + g + 8) * H_ + h) * D_;
    #pragma unroll
    for (int dt = 0; dt < 8; dt++){
        int col = dt * 8 + 2 * t;
        float2 r0 = make_float2(o[dt][0] * inv0, o[dt][1] * inv0);
        float2 r1 = make_float2(o[dt][2] * inv1, o[dt][3] * inv1);
        *(float2*)(o0 + col) = r0;
        *(float2*)(o8 + col) = r1;
    }
}

extern "C" void kernel_launch(void* const* d_in, const int* in_sizes, int n_in,
                              void* d_out, int out_size)
{
    const float* q    = (const float*)d_in[0];
    const float* k    = (const float*)d_in[1];
    const float* v    = (const float*)d_in[2];
    const int*   mask = (const int*)d_in[3];
    float*       out  = (float*)d_out;

    cvt_kernel<<<(3 * N4 + 255) / 256, 256>>>((const float4*)q, (const float4*)k,
                                              (const float4*)v);

    cudaFuncSetAttribute(attn_hmma_kernel,
                         cudaFuncAttributeMaxDynamicSharedMemorySize, SMEMB);
    dim3 grid(S_ / BQ, H_, B_);
    attn_hmma_kernel<<<grid, 256, SMEMB>>>(mask, out);
}

// round 4
// speedup vs baseline: 2.1432x; 1.2046x over previous
#include <cuda_runtime.h>
#include <cuda_bf16.h>
#include <cstdint>
#include <math.h>

#define B_ 4
#define S_ 2048
#define H_ 16
#define D_ 64
#define BQ 128
#define BK 64
#define NTILE (S_/BK)            // 32
#define NELEM (B_*H_*S_*D_)      // 8388608
#define N4 (NELEM/4)             // 2097152

// Pre-converted bf16 hi/lo operands, head-major [b][h][s][d]
__device__ __nv_bfloat16 g_Qhi[NELEM];
__device__ __nv_bfloat16 g_Qlo[NELEM];
__device__ __nv_bfloat16 g_Khi[NELEM];
__device__ __nv_bfloat16 g_Klo[NELEM];
__device__ __nv_bfloat16 g_Vhi[NELEM];
__device__ __nv_bfloat16 g_Vlo[NELEM];

// ---------------- conversion / layout pre-pass ----------------
__global__ void cvt_kernel(const float4* __restrict__ q,
                           const float4* __restrict__ k,
                           const float4* __restrict__ v)
{
    int j = blockIdx.x * blockDim.x + threadIdx.x;
    if (j >= 3 * N4) return;
    int tsel = j / N4;
    int i = j - tsel * N4;

    const float4*  src = (tsel == 0) ? q : (tsel == 1) ? k : v;
    __nv_bfloat16* dh  = (tsel == 0) ? g_Qhi : (tsel == 1) ? g_Khi : g_Vhi;
    __nv_bfloat16* dl  = (tsel == 0) ? g_Qlo : (tsel == 1) ? g_Klo : g_Vlo;
    const float scale  = (tsel == 0) ? 0.125f : 1.0f;

    // src linear float4 index i over [b][s][h][c4]
    int c4 = i & 15, h = (i >> 4) & 15, s = (i >> 8) & 2047, b = i >> 19;
    float4 x = src[i];
    x.x *= scale; x.y *= scale; x.z *= scale; x.w *= scale;

    __nv_bfloat162 h01 = __floats2bfloat162_rn(x.x, x.y);
    __nv_bfloat162 h23 = __floats2bfloat162_rn(x.z, x.w);
    __nv_bfloat162 l01 = __floats2bfloat162_rn(x.x - __bfloat162float(h01.x),
                                               x.y - __bfloat162float(h01.y));
    __nv_bfloat162 l23 = __floats2bfloat162_rn(x.z - __bfloat162float(h23.x),
                                               x.w - __bfloat162float(h23.y));

    size_t p = ((size_t)(b * 16 + h) * 2048 + s) * 64 + c4 * 4;
    *(__nv_bfloat162*)(dh + p)     = h01;
    *(__nv_bfloat162*)(dh + p + 2) = h23;
    *(__nv_bfloat162*)(dl + p)     = l01;
    *(__nv_bfloat162*)(dl + p + 2) = l23;
}

// ---------------- mma / ldmatrix / cp.async primitives ----------------
__device__ __forceinline__ void hmma(float* c, const uint32_t* a, uint32_t b0, uint32_t b1){
    asm("mma.sync.aligned.m16n8k16.row.col.f32.bf16.bf16.f32 "
        "{%0,%1,%2,%3}, {%4,%5,%6,%7}, {%8,%9}, {%0,%1,%2,%3};"
        : "+f"(c[0]), "+f"(c[1]), "+f"(c[2]), "+f"(c[3])
        : "r"(a[0]), "r"(a[1]), "r"(a[2]), "r"(a[3]), "r"(b0), "r"(b1));
}
__device__ __forceinline__ void ldsm4(uint32_t* r, uint32_t a){
    asm volatile("ldmatrix.sync.aligned.m8n8.x4.shared.b16 {%0,%1,%2,%3}, [%4];"
        : "=r"(r[0]), "=r"(r[1]), "=r"(r[2]), "=r"(r[3]) : "r"(a));
}
__device__ __forceinline__ void ldsm4t(uint32_t* r, uint32_t a){
    asm volatile("ldmatrix.sync.aligned.m8n8.x4.trans.shared.b16 {%0,%1,%2,%3}, [%4];"
        : "=r"(r[0]), "=r"(r[1]), "=r"(r[2]), "=r"(r[3]) : "r"(a));
}
__device__ __forceinline__ void cp16(uint32_t dst, const void* src){
    asm volatile("cp.async.cg.shared.global [%0], [%1], 16;" :: "r"(dst), "l"(src));
}
__device__ __forceinline__ void cp_commit(){ asm volatile("cp.async.commit_group;"); }
template<int N> __device__ __forceinline__ void cp_wait(){
    asm volatile("cp.async.wait_group %0;" :: "n"(N));
}
__device__ __forceinline__ uint32_t smem_u32(const void* p){
    uint32_t a;
    asm("{ .reg .u64 t; cvta.to.shared.u64 t, %1; cvt.u32.u64 %0, t; }" : "=r"(a) : "l"(p));
    return a;
}
__device__ __forceinline__ void split2(float x, float y, uint32_t& hi, uint32_t& lo){
    __nv_bfloat162 h = __floats2bfloat162_rn(x, y);
    __nv_bfloat162 l = __floats2bfloat162_rn(x - __bfloat162float(h.x),
                                             y - __bfloat162float(h.y));
    hi = *(uint32_t*)&h; lo = *(uint32_t*)&l;
}

// smem: 2 stages x 4 tiles (Khi,Klo,Vhi,Vlo), each 64 rows x 144B (72 bf16, pad 8)
#define TILEB   9216
#define STAGEB  36864
#define SMEMB   (2*STAGEB)   // 73728 per CTA; 2 CTAs/SM = 147456

__device__ __forceinline__ void issue_tile(uint32_t smbase, int st,
    const __nv_bfloat16* Kh, const __nv_bfloat16* Kl,
    const __nv_bfloat16* Vh, const __nv_bfloat16* Vl, int k0, int tid)
{
    const char* srcs[4] = {
        (const char*)(Kh + (size_t)k0 * 64), (const char*)(Kl + (size_t)k0 * 64),
        (const char*)(Vh + (size_t)k0 * 64), (const char*)(Vl + (size_t)k0 * 64) };
    uint32_t dst0 = smbase + st * STAGEB;
    #pragma unroll
    for (int i = 0; i < 8; i++){
        int sub = i >> 1;
        int c   = ((i & 1) << 8) + tid;   // 0..511 chunk within sub-tile
        int r   = c >> 3, o = c & 7;
        cp16(dst0 + sub * TILEB + r * 144 + o * 16, srcs[sub] + r * 128 + o * 16);
    }
    cp_commit();
}

// ---------------- main flash-attention kernel ----------------
__global__ __launch_bounds__(256, 2)
void attn_hmma_kernel(const int* __restrict__ mask, float* __restrict__ out)
{
    extern __shared__ char smc[];
    const uint32_t smbase = smem_u32(smc);
    const int tid = threadIdx.x;
    const int w = tid >> 5, lane = tid & 31;
    const int g = lane >> 2, t = lane & 3;
    const int qt = blockIdx.x, h = blockIdx.y, b = blockIdx.z;
    const int bh = b * H_ + h;
    const int q0 = qt * BQ;
    const int qrow0 = q0 + w * 16;

    const __nv_bfloat16* Kh = g_Khi + (size_t)bh * S_ * 64;
    const __nv_bfloat16* Kl = g_Klo + (size_t)bh * S_ * 64;
    const __nv_bfloat16* Vh = g_Vhi + (size_t)bh * S_ * 64;
    const __nv_bfloat16* Vl = g_Vlo + (size_t)bh * S_ * 64;

    // ---- Q fragments from gmem (one-time): aQ[kc][0..3] ----
    uint32_t aQh[4][4], aQl[4][4];
    {
        const __nv_bfloat16* Qh = g_Qhi + ((size_t)bh * S_ + qrow0) * 64;
        const __nv_bfloat16* Ql = g_Qlo + ((size_t)bh * S_ + qrow0) * 64;
        #pragma unroll
        for (int kc = 0; kc < 4; kc++){
            int c0 = kc * 16 + 2 * t;
            aQh[kc][0] = *(const uint32_t*)(Qh + g * 64 + c0);
            aQh[kc][1] = *(const uint32_t*)(Qh + (g + 8) * 64 + c0);
            aQh[kc][2] = *(const uint32_t*)(Qh + g * 64 + c0 + 8);
            aQh[kc][3] = *(const uint32_t*)(Qh + (g + 8) * 64 + c0 + 8);
            aQl[kc][0] = *(const uint32_t*)(Ql + g * 64 + c0);
            aQl[kc][1] = *(const uint32_t*)(Ql + (g + 8) * 64 + c0);
            aQl[kc][2] = *(const uint32_t*)(Ql + g * 64 + c0 + 8);
            aQl[kc][3] = *(const uint32_t*)(Ql + (g + 8) * 64 + c0 + 8);
        }
    }

    const int* mr0 = mask + ((size_t)bh * S_ + qrow0 + g) * S_;
    const int* mr8 = mr0 + 8 * S_;

    float o[8][4];
    #pragma unroll
    for (int i = 0; i < 8; i++)
        #pragma unroll
        for (int j = 0; j < 4; j++) o[i][j] = 0.f;
    float lsum0 = 0.f, lsum1 = 0.f;

    // ldmatrix lane address components
    const int krow_l = (lane & 7) + ((lane >> 4) << 3);
    const uint32_t kcol_l = ((lane >> 3) & 1) * 16;
    const int vrow_l = (lane & 7) + (((lane >> 3) & 1) << 3);
    const uint32_t vcol_l = (lane >> 4) * 16;

    issue_tile(smbase, 0, Kh, Kl, Vh, Vl, 0, tid);

    for (int tt = 0; tt < NTILE; tt++){
        const int k0 = tt * BK;
        const int st = tt & 1;
        if (tt + 1 < NTILE){
            issue_tile(smbase, (tt + 1) & 1, Kh, Kl, Vh, Vl, k0 + BK, tid);
            cp_wait<1>();
        } else {
            cp_wait<0>();
        }
        __syncthreads();

        const uint32_t kbh = smbase + st * STAGEB;
        const uint32_t kbl = kbh + TILEB;
        const uint32_t vbh = kbh + 2 * TILEB;
        const uint32_t vbl = kbh + 3 * TILEB;

        // one-chunk-ahead mask prefetch
        int2 mcur[4], mnxt[4];
        {
            int cb = k0 + 2 * t;
            mcur[0] = *(const int2*)(mr0 + cb);
            mcur[1] = *(const int2*)(mr8 + cb);
            mcur[2] = *(const int2*)(mr0 + cb + 8);
            mcur[3] = *(const int2*)(mr8 + cb + 8);
        }

        #pragma unroll
        for (int c = 0; c < 4; c++){
            if (c < 3){
                int cb = k0 + (c + 1) * 16 + 2 * t;
                mnxt[0] = *(const int2*)(mr0 + cb);
                mnxt[1] = *(const int2*)(mr8 + cb);
                mnxt[2] = *(const int2*)(mr0 + cb + 8);
                mnxt[3] = *(const int2*)(mr8 + cb + 8);
            }

            // ---- QK with 4 independent accumulator chains (depth <= 8) ----
            // sA*: Qh@Kh + Ql@Kh   sB*: Qh@Kl
            float sA0[4] = {0.f, 0.f, 0.f, 0.f};
            float sA1[4] = {0.f, 0.f, 0.f, 0.f};
            float sB0[4] = {0.f, 0.f, 0.f, 0.f};
            float sB1[4] = {0.f, 0.f, 0.f, 0.f};
            const uint32_t ka_h = kbh + (uint32_t)(c * 16 + krow_l) * 144 + kcol_l;
            const uint32_t ka_l = kbl + (uint32_t)(c * 16 + krow_l) * 144 + kcol_l;
            #pragma unroll
            for (int kc = 0; kc < 4; kc++){
                uint32_t bhf[4], blf[4];
                ldsm4(bhf, ka_h + kc * 32);
                ldsm4(blf, ka_l + kc * 32);
                hmma(sA0, aQh[kc], bhf[0], bhf[1]);
                hmma(sA1, aQh[kc], bhf[2], bhf[3]);
                hmma(sB0, aQh[kc], blf[0], blf[1]);
                hmma(sB1, aQh[kc], blf[2], blf[3]);
                hmma(sA0, aQl[kc], bhf[0], bhf[1]);
                hmma(sA1, aQl[kc], bhf[2], bhf[3]);
            }

            // ---- mask + exp (masked -> p = 1.0, faithful to exp(1e-20)) ----
            float p00 = mcur[0].x ? __expf(sA0[0] + sB0[0]) : 1.f;
            float p01 = mcur[0].y ? __expf(sA0[1] + sB0[1]) : 1.f;
            float p02 = mcur[1].x ? __expf(sA0[2] + sB0[2]) : 1.f;
            float p03 = mcur[1].y ? __expf(sA0[3] + sB0[3]) : 1.f;
            float p10 = mcur[2].x ? __expf(sA1[0] + sB1[0]) : 1.f;
            float p11 = mcur[2].y ? __expf(sA1[1] + sB1[1]) : 1.f;
            float p12 = mcur[3].x ? __expf(sA1[2] + sB1[2]) : 1.f;
            float p13 = mcur[3].y ? __expf(sA1[3] + sB1[3]) : 1.f;
            lsum0 += (p00 + p01) + (p10 + p11);
            lsum1 += (p02 + p03) + (p12 + p13);

            // ---- P -> A-fragments (hi/lo) ----
            uint32_t ph[4], pl[4];
            split2(p00, p01, ph[0], pl[0]);
            split2(p02, p03, ph[1], pl[1]);
            split2(p10, p11, ph[2], pl[2]);
            split2(p12, p13, ph[3], pl[3]);

            // ---- PV: O += Ph@Vh + Ph@Vl + Pl@Vh (8 indep chains, depth 3) ----
            const uint32_t va_h = vbh + (uint32_t)(c * 16 + vrow_l) * 144 + vcol_l;
            const uint32_t va_l = vbl + (uint32_t)(c * 16 + vrow_l) * 144 + vcol_l;
            #pragma unroll
            for (int dt2 = 0; dt2 < 4; dt2++){
                uint32_t bhf[4], blf[4];
                ldsm4t(bhf, va_h + dt2 * 32);
                ldsm4t(blf, va_l + dt2 * 32);
                hmma(o[2 * dt2],     ph, bhf[0], bhf[1]);
                hmma(o[2 * dt2 + 1], ph, bhf[2], bhf[3]);
                hmma(o[2 * dt2],     ph, blf[0], blf[1]);
                hmma(o[2 * dt2 + 1], ph, blf[2], blf[3]);
                hmma(o[2 * dt2],     pl, bhf[0], bhf[1]);
                hmma(o[2 * dt2 + 1], pl, bhf[2], bhf[3]);
            }

            if (c < 3){
                #pragma unroll
                for (int i = 0; i < 4; i++) mcur[i] = mnxt[i];
            }
        }
        __syncthreads();
    }

    // ---- row-sum reduce over the 4 lanes of each row group ----
    lsum0 += __shfl_xor_sync(0xffffffffu, lsum0, 1);
    lsum0 += __shfl_xor_sync(0xffffffffu, lsum0, 2);
    lsum1 += __shfl_xor_sync(0xffffffffu, lsum1, 1);
    lsum1 += __shfl_xor_sync(0xffffffffu, lsum1, 2);
    const float inv0 = 1.0f / lsum0;
    const float inv1 = 1.0f / lsum1;

    // ---- store O: out[b][q][h][d] ----
    float* o0 = out + (((size_t)b * S_ + qrow0 + g) * H_ + h) * D_;
    float* o8 = out + (((size_t)b * S_ + qrow0 + g + 8) * H_ + h) * D_;
    #pragma unroll
    for (int dt = 0; dt < 8; dt++){
        int col = dt * 8 + 2 * t;
        float2 r0 = make_float2(o[dt][0] * inv0, o[dt][1] * inv0);
        float2 r1 = make_float2(o[dt][2] * inv1, o[dt][3] * inv1);
        *(float2*)(o0 + col) = r0;
        *(float2*)(o8 + col) = r1;
    }
}

extern "C" void kernel_launch(void* const* d_in, const int* in_sizes, int n_in,
                              void* d_out, int out_size)
{
    const float* q    = (const float*)d_in[0];
    const float* k    = (const float*)d_in[1];
    const float* v    = (const float*)d_in[2];
    const int*   mask = (const int*)d_in[3];
    float*       out  = (float*)d_out;

    cvt_kernel<<<(3 * N4 + 255) / 256, 256>>>((const float4*)q, (const float4*)k,
                                              (const float4*)v);

    cudaFuncSetAttribute(attn_hmma_kernel,
                         cudaFuncAttributeMaxDynamicSharedMemorySize, SMEMB);
    dim3 grid(S_ / BQ, H_, B_);
    attn_hmma_kernel<<<grid, 256, SMEMB>>>(mask, out);
}

// round 5
// speedup vs baseline: 3.0816x; 1.4379x over previous
#include <cuda_runtime.h>
#include <cuda_fp16.h>
#include <cstdint>
#include <math.h>

#define B_ 4
#define S_ 2048
#define H_ 16
#define D_ 64
#define BQ 128
#define BK 64
#define NTILE (S_/BK)            // 32
#define NELEM (B_*H_*S_*D_)      // 8388608
#define N4 (NELEM/4)             // 2097152

// Pre-converted fp16 operands, head-major [b][h][s][d]
__device__ __half g_Qh[NELEM];
__device__ __half g_Kh[NELEM];
__device__ __half g_Kl[NELEM];
__device__ __half g_Vh[NELEM];
__device__ __half g_Vl[NELEM];

// ---------------- conversion / layout pre-pass ----------------
__global__ void cvt_kernel(const float4* __restrict__ q,
                           const float4* __restrict__ k,
                           const float4* __restrict__ v)
{
    int j = blockIdx.x * blockDim.x + threadIdx.x;
    if (j >= 3 * N4) return;
    int tsel = j / N4;
    int i = j - tsel * N4;

    const float4* src = (tsel == 0) ? q : (tsel == 1) ? k : v;
    __half* dh = (tsel == 0) ? g_Qh : (tsel == 1) ? g_Kh : g_Vh;
    __half* dl = (tsel == 1) ? g_Kl : g_Vl;   // unused for Q
    const float scale = (tsel == 0) ? 0.125f : 1.0f;

    // src linear float4 index i over [b][s][h][c4]
    int c4 = i & 15, h = (i >> 4) & 15, s = (i >> 8) & 2047, b = i >> 19;
    float4 x = src[i];
    x.x *= scale; x.y *= scale; x.z *= scale; x.w *= scale;

    __half2 h01 = __floats2half2_rn(x.x, x.y);
    __half2 h23 = __floats2half2_rn(x.z, x.w);

    size_t p = ((size_t)(b * 16 + h) * 2048 + s) * 64 + c4 * 4;
    *(__half2*)(dh + p)     = h01;
    *(__half2*)(dh + p + 2) = h23;

    if (tsel != 0){
        __half2 l01 = __floats2half2_rn(x.x - __half2float(h01.x),
                                        x.y - __half2float(h01.y));
        __half2 l23 = __floats2half2_rn(x.z - __half2float(h23.x),
                                        x.w - __half2float(h23.y));
        *(__half2*)(dl + p)     = l01;
        *(__half2*)(dl + p + 2) = l23;
    }
}

// ---------------- mma / ldmatrix / cp.async primitives ----------------
__device__ __forceinline__ void hmma(float* c, const uint32_t* a, uint32_t b0, uint32_t b1){
    asm("mma.sync.aligned.m16n8k16.row.col.f32.f16.f16.f32 "
        "{%0,%1,%2,%3}, {%4,%5,%6,%7}, {%8,%9}, {%0,%1,%2,%3};"
        : "+f"(c[0]), "+f"(c[1]), "+f"(c[2]), "+f"(c[3])
        : "r"(a[0]), "r"(a[1]), "r"(a[2]), "r"(a[3]), "r"(b0), "r"(b1));
}
__device__ __forceinline__ void ldsm4(uint32_t* r, uint32_t a){
    asm volatile("ldmatrix.sync.aligned.m8n8.x4.shared.b16 {%0,%1,%2,%3}, [%4];"
        : "=r"(r[0]), "=r"(r[1]), "=r"(r[2]), "=r"(r[3]) : "r"(a));
}
__device__ __forceinline__ void ldsm4t(uint32_t* r, uint32_t a){
    asm volatile("ldmatrix.sync.aligned.m8n8.x4.trans.shared.b16 {%0,%1,%2,%3}, [%4];"
        : "=r"(r[0]), "=r"(r[1]), "=r"(r[2]), "=r"(r[3]) : "r"(a));
}
__device__ __forceinline__ void cp16(uint32_t dst, const void* src){
    asm volatile("cp.async.cg.shared.global [%0], [%1], 16;" :: "r"(dst), "l"(src));
}
__device__ __forceinline__ void cp_commit(){ asm volatile("cp.async.commit_group;"); }
template<int N> __device__ __forceinline__ void cp_wait(){
    asm volatile("cp.async.wait_group %0;" :: "n"(N));
}
__device__ __forceinline__ uint32_t smem_u32(const void* p){
    uint32_t a;
    asm("{ .reg .u64 t; cvta.to.shared.u64 t, %1; cvt.u32.u64 %0, t; }" : "=r"(a) : "l"(p));
    return a;
}

// smem: 2 stages x 4 tiles (Kh,Kl,Vh,Vl), each 64 rows x 144B (72 fp16, pad 8)
#define TILEB   9216
#define STAGEB  36864
#define SMEMB   (2*STAGEB)   // 73728 per CTA; 2 CTAs/SM

__device__ __forceinline__ void issue_tile(uint32_t smbase, int st,
    const __half* Kh, const __half* Kl,
    const __half* Vh, const __half* Vl, int k0, int tid)
{
    const char* srcs[4] = {
        (const char*)(Kh + (size_t)k0 * 64), (const char*)(Kl + (size_t)k0 * 64),
        (const char*)(Vh + (size_t)k0 * 64), (const char*)(Vl + (size_t)k0 * 64) };
    uint32_t dst0 = smbase + st * STAGEB;
    #pragma unroll
    for (int i = 0; i < 8; i++){
        int sub = i >> 1;
        int c   = ((i & 1) << 8) + tid;   // 0..511 chunk within sub-tile
        int r   = c >> 3, o = c & 7;
        cp16(dst0 + sub * TILEB + r * 144 + o * 16, srcs[sub] + r * 128 + o * 16);
    }
    cp_commit();
}

// ---------------- main flash-attention kernel ----------------
__global__ __launch_bounds__(256, 2)
void attn_hmma_kernel(const int* __restrict__ mask, float* __restrict__ out)
{
    extern __shared__ char smc[];
    const uint32_t smbase = smem_u32(smc);
    const int tid = threadIdx.x;
    const int w = tid >> 5, lane = tid & 31;
    const int g = lane >> 2, t = lane & 3;
    const int qt = blockIdx.x, h = blockIdx.y, b = blockIdx.z;
    const int bh = b * H_ + h;
    const int q0 = qt * BQ;
    const int qrow0 = q0 + w * 16;

    const __half* Kh = g_Kh + (size_t)bh * S_ * 64;
    const __half* Kl = g_Kl + (size_t)bh * S_ * 64;
    const __half* Vh = g_Vh + (size_t)bh * S_ * 64;
    const __half* Vl = g_Vl + (size_t)bh * S_ * 64;

    // ---- Q fragments from gmem (one-time): aQ[kc][0..3] ----
    uint32_t aQ[4][4];
    {
        const __half* Qh = g_Qh + ((size_t)bh * S_ + qrow0) * 64;
        #pragma unroll
        for (int kc = 0; kc < 4; kc++){
            int c0 = kc * 16 + 2 * t;
            aQ[kc][0] = *(const uint32_t*)(Qh + g * 64 + c0);
            aQ[kc][1] = *(const uint32_t*)(Qh + (g + 8) * 64 + c0);
            aQ[kc][2] = *(const uint32_t*)(Qh + g * 64 + c0 + 8);
            aQ[kc][3] = *(const uint32_t*)(Qh + (g + 8) * 64 + c0 + 8);
        }
    }

    const int* mr0 = mask + ((size_t)bh * S_ + qrow0 + g) * S_;
    const int* mr8 = mr0 + 8 * S_;

    float o[8][4];
    #pragma unroll
    for (int i = 0; i < 8; i++)
        #pragma unroll
        for (int j = 0; j < 4; j++) o[i][j] = 0.f;
    float lsum0 = 0.f, lsum1 = 0.f;

    // ldmatrix lane address components
    const int krow_l = (lane & 7) + ((lane >> 4) << 3);
    const uint32_t kcol_l = ((lane >> 3) & 1) * 16;
    const int vrow_l = (lane & 7) + (((lane >> 3) & 1) << 3);
    const uint32_t vcol_l = (lane >> 4) * 16;

    issue_tile(smbase, 0, Kh, Kl, Vh, Vl, 0, tid);

    for (int tt = 0; tt < NTILE; tt++){
        const int k0 = tt * BK;
        const int st = tt & 1;
        if (tt + 1 < NTILE){
            issue_tile(smbase, (tt + 1) & 1, Kh, Kl, Vh, Vl, k0 + BK, tid);
            cp_wait<1>();
        } else {
            cp_wait<0>();
        }
        __syncthreads();

        const uint32_t kbh = smbase + st * STAGEB;
        const uint32_t kbl = kbh + TILEB;
        const uint32_t vbh = kbh + 2 * TILEB;
        const uint32_t vbl = kbh + 3 * TILEB;

        // one-chunk-ahead mask prefetch
        int2 mcur[4], mnxt[4];
        {
            int cb = k0 + 2 * t;
            mcur[0] = *(const int2*)(mr0 + cb);
            mcur[1] = *(const int2*)(mr8 + cb);
            mcur[2] = *(const int2*)(mr0 + cb + 8);
            mcur[3] = *(const int2*)(mr8 + cb + 8);
        }

        #pragma unroll
        for (int c = 0; c < 4; c++){
            if (c < 3){
                int cb = k0 + (c + 1) * 16 + 2 * t;
                mnxt[0] = *(const int2*)(mr0 + cb);
                mnxt[1] = *(const int2*)(mr8 + cb);
                mnxt[2] = *(const int2*)(mr0 + cb + 8);
                mnxt[3] = *(const int2*)(mr8 + cb + 8);
            }

            // ---- QK, fp16 2-product: S = Qh@Kh + Qh@Kl (4 indep chains) ----
            float sA0[4] = {0.f, 0.f, 0.f, 0.f};
            float sA1[4] = {0.f, 0.f, 0.f, 0.f};
            float sB0[4] = {0.f, 0.f, 0.f, 0.f};
            float sB1[4] = {0.f, 0.f, 0.f, 0.f};
            const uint32_t ka_h = kbh + (uint32_t)(c * 16 + krow_l) * 144 + kcol_l;
            const uint32_t ka_l = kbl + (uint32_t)(c * 16 + krow_l) * 144 + kcol_l;
            #pragma unroll
            for (int kc = 0; kc < 4; kc++){
                uint32_t bhf[4], blf[4];
                ldsm4(bhf, ka_h + kc * 32);
                ldsm4(blf, ka_l + kc * 32);
                hmma(sA0, aQ[kc], bhf[0], bhf[1]);
                hmma(sA1, aQ[kc], bhf[2], bhf[3]);
                hmma(sB0, aQ[kc], blf[0], blf[1]);
                hmma(sB1, aQ[kc], blf[2], blf[3]);
            }

            // ---- mask + exp (masked -> p = 1.0, faithful to exp(1e-20)) ----
            float p00 = mcur[0].x ? __expf(sA0[0] + sB0[0]) : 1.f;
            float p01 = mcur[0].y ? __expf(sA0[1] + sB0[1]) : 1.f;
            float p02 = mcur[1].x ? __expf(sA0[2] + sB0[2]) : 1.f;
            float p03 = mcur[1].y ? __expf(sA0[3] + sB0[3]) : 1.f;
            float p10 = mcur[2].x ? __expf(sA1[0] + sB1[0]) : 1.f;
            float p11 = mcur[2].y ? __expf(sA1[1] + sB1[1]) : 1.f;
            float p12 = mcur[3].x ? __expf(sA1[2] + sB1[2]) : 1.f;
            float p13 = mcur[3].y ? __expf(sA1[3] + sB1[3]) : 1.f;
            lsum0 += (p00 + p01) + (p10 + p11);
            lsum1 += (p02 + p03) + (p12 + p13);

            // ---- P -> fp16 A-fragments (single precision level) ----
            uint32_t ph[4];
            { __half2 x = __floats2half2_rn(p00, p01); ph[0] = *(uint32_t*)&x; }
            { __half2 x = __floats2half2_rn(p02, p03); ph[1] = *(uint32_t*)&x; }
            { __half2 x = __floats2half2_rn(p10, p11); ph[2] = *(uint32_t*)&x; }
            { __half2 x = __floats2half2_rn(p12, p13); ph[3] = *(uint32_t*)&x; }

            // ---- PV, fp16 2-product: O += Ph@Vh + Ph@Vl (8 chains, depth 2) ----
            const uint32_t va_h = vbh + (uint32_t)(c * 16 + vrow_l) * 144 + vcol_l;
            const uint32_t va_l = vbl + (uint32_t)(c * 16 + vrow_l) * 144 + vcol_l;
            #pragma unroll
            for (int dt2 = 0; dt2 < 4; dt2++){
                uint32_t bhf[4], blf[4];
                ldsm4t(bhf, va_h + dt2 * 32);
                ldsm4t(blf, va_l + dt2 * 32);
                hmma(o[2 * dt2],     ph, bhf[0], bhf[1]);
                hmma(o[2 * dt2 + 1], ph, bhf[2], bhf[3]);
                hmma(o[2 * dt2],     ph, blf[0], blf[1]);
                hmma(o[2 * dt2 + 1], ph, blf[2], blf[3]);
            }

            if (c < 3){
                #pragma unroll
                for (int i = 0; i < 4; i++) mcur[i] = mnxt[i];
            }
        }
        __syncthreads();
    }

    // ---- row-sum reduce over the 4 lanes of each row group ----
    lsum0 += __shfl_xor_sync(0xffffffffu, lsum0, 1);
    lsum0 += __shfl_xor_sync(0xffffffffu, lsum0, 2);
    lsum1 += __shfl_xor_sync(0xffffffffu, lsum1, 1);
    lsum1 += __shfl_xor_sync(0xffffffffu, lsum1, 2);
    const float inv0 = 1.0f / lsum0;
    const float inv1 = 1.0f / lsum1;

    // ---- store O: out[b][q][h][d] ----
    float* o0 = out + (((size_t)b * S_ + qrow0 + g) * H_ + h) * D_;
    float* o8 = out + (((size_t)b * S_ + qrow0 + g + 8) * H_ + h) * D_;
    #pragma unroll
    for (int dt = 0; dt < 8; dt++){
        int col = dt * 8 + 2 * t;
        float2 r0 = make_float2(o[dt][0] * inv0, o[dt][1] * inv0);
        float2 r1 = make_float2(o[dt][2] * inv1, o[dt][3] * inv1);
        *(float2*)(o0 + col) = r0;
        *(float2*)(o8 + col) = r1;
    }
}

extern "C" void kernel_launch(void* const* d_in, const int* in_sizes, int n_in,
                              void* d_out, int out_size)
{
    const float* q    = (const float*)d_in[0];
    const float* k    = (const float*)d_in[1];
    const float* v    = (const float*)d_in[2];
    const int*   mask = (const int*)d_in[3];
    float*       out  = (float*)d_out;

    cvt_kernel<<<(3 * N4 + 255) / 256, 256>>>((const float4*)q, (const float4*)k,
                                              (const float4*)v);

    cudaFuncSetAttribute(attn_hmma_kernel,
                         cudaFuncAttributeMaxDynamicSharedMemorySize, SMEMB);
    dim3 grid(S_ / BQ, H_, B_);
    attn_hmma_kernel<<<grid, 256, SMEMB>>>(mask, out);
}

// round 7
// speedup vs baseline: 3.5057x; 1.1376x over previous
#include <cuda_runtime.h>
#include <cuda_fp16.h>
#include <cstdint>
#include <math.h>

#define B_ 4
#define S_ 2048
#define H_ 16
#define D_ 64
#define BQ 128
#define BK 64
#define NTILE (S_/BK)            // 32
#define NELEM (B_*H_*S_*D_)      // 8388608
#define N4 (NELEM/4)             // 2097152

// Pre-converted fp16 operands, head-major [b][h][s][d]
__device__ __half g_Qh[NELEM];
__device__ __half g_Kh[NELEM];
__device__ __half g_Kl[NELEM];
__device__ __half g_Vh[NELEM];
__device__ __half g_Vl[NELEM];

// ---------------- conversion / layout pre-pass ----------------
__global__ void cvt_kernel(const float4* __restrict__ q,
                           const float4* __restrict__ k,
                           const float4* __restrict__ v)
{
    int j = blockIdx.x * blockDim.x + threadIdx.x;
    if (j >= 3 * N4) return;
    int tsel = j / N4;
    int i = j - tsel * N4;

    const float4* src = (tsel == 0) ? q : (tsel == 1) ? k : v;
    __half* dh = (tsel == 0) ? g_Qh : (tsel == 1) ? g_Kh : g_Vh;
    __half* dl = (tsel == 1) ? g_Kl : g_Vl;   // unused for Q
    const float scale = (tsel == 0) ? 0.125f : 1.0f;

    // src linear float4 index i over [b][s][h][c4]
    int c4 = i & 15, h = (i >> 4) & 15, s = (i >> 8) & 2047, b = i >> 19;
    float4 x = src[i];
    x.x *= scale; x.y *= scale; x.z *= scale; x.w *= scale;

    __half2 h01 = __floats2half2_rn(x.x, x.y);
    __half2 h23 = __floats2half2_rn(x.z, x.w);

    size_t p = ((size_t)(b * 16 + h) * 2048 + s) * 64 + c4 * 4;
    *(__half2*)(dh + p)     = h01;
    *(__half2*)(dh + p + 2) = h23;

    if (tsel != 0){
        __half2 l01 = __floats2half2_rn(x.x - __half2float(h01.x),
                                        x.y - __half2float(h01.y));
        __half2 l23 = __floats2half2_rn(x.z - __half2float(h23.x),
                                        x.w - __half2float(h23.y));
        *(__half2*)(dl + p)     = l01;
        *(__half2*)(dl + p + 2) = l23;
    }
}

// ---------------- mma / ldmatrix / cp.async primitives ----------------
__device__ __forceinline__ void hmma(float* c, const uint32_t* a, uint32_t b0, uint32_t b1){
    asm("mma.sync.aligned.m16n8k16.row.col.f32.f16.f16.f32 "
        "{%0,%1,%2,%3}, {%4,%5,%6,%7}, {%8,%9}, {%0,%1,%2,%3};"
        : "+f"(c[0]), "+f"(c[1]), "+f"(c[2]), "+f"(c[3])
        : "r"(a[0]), "r"(a[1]), "r"(a[2]), "r"(a[3]), "r"(b0), "r"(b1));
}
__device__ __forceinline__ void ldsm4(uint32_t* r, uint32_t a){
    asm volatile("ldmatrix.sync.aligned.m8n8.x4.shared.b16 {%0,%1,%2,%3}, [%4];"
        : "=r"(r[0]), "=r"(r[1]), "=r"(r[2]), "=r"(r[3]) : "r"(a));
}
__device__ __forceinline__ void ldsm4t(uint32_t* r, uint32_t a){
    asm volatile("ldmatrix.sync.aligned.m8n8.x4.trans.shared.b16 {%0,%1,%2,%3}, [%4];"
        : "=r"(r[0]), "=r"(r[1]), "=r"(r[2]), "=r"(r[3]) : "r"(a));
}
__device__ __forceinline__ void cp16(uint32_t dst, const void* src){
    asm volatile("cp.async.cg.shared.global [%0], [%1], 16;" :: "r"(dst), "l"(src));
}
__device__ __forceinline__ void cp_commit(){ asm volatile("cp.async.commit_group;"); }
template<int N> __device__ __forceinline__ void cp_wait(){
    asm volatile("cp.async.wait_group %0;" :: "n"(N));
}
__device__ __forceinline__ uint32_t smem_u32(const void* p){
    uint32_t a;
    asm("{ .reg .u64 t; cvta.to.shared.u64 t, %1; cvt.u32.u64 %0, t; }" : "=r"(a) : "l"(p));
    return a;
}

// smem: 2 stages x 4 KV tiles (Kh,Kl,Vh,Vl), each 64 rows x 144B, then mask tile
#define TILEB   9216
#define STAGEB  36864
#define MASKB   (2*STAGEB)           // 73728
#define SMEMB   (MASKB + 32768)      // 106496 per CTA; 2 CTAs/SM = 212992

__device__ __forceinline__ void issue_tile(uint32_t smbase, int st,
    const __half* Kh, const __half* Kl,
    const __half* Vh, const __half* Vl, int k0, int tid)
{
    const char* srcs[4] = {
        (const char*)(Kh + (size_t)k0 * 64), (const char*)(Kl + (size_t)k0 * 64),
        (const char*)(Vh + (size_t)k0 * 64), (const char*)(Vl + (size_t)k0 * 64) };
    uint32_t dst0 = smbase + st * STAGEB;
    #pragma unroll
    for (int i = 0; i < 8; i++){
        int sub = i >> 1;
        int c   = ((i & 1) << 8) + tid;   // 0..511 chunk within sub-tile
        int r   = c >> 3, o = c & 7;
        cp16(dst0 + sub * TILEB + r * 144 + o * 16, srcs[sub] + r * 128 + o * 16);
    }
    cp_commit();
}

// mask tile: 128 rows x 64 ints, row stride 256B, 16B chunks XOR-swizzled by row&7
__device__ __forceinline__ void issue_mask(uint32_t smbase, const int* mg, int tid)
{
    #pragma unroll
    for (int i = 0; i < 8; i++){
        int cl  = tid + i * 256;          // 0..2047
        int row = cl >> 4, cc = cl & 15;
        uint32_t dst = smbase + MASKB + row * 256 + (uint32_t)((cc ^ (row & 7)) << 4);
        cp16(dst, (const char*)(mg + (size_t)row * S_ + cc * 4));
    }
    cp_commit();
}

// ---------------- main flash-attention kernel ----------------
__global__ __launch_bounds__(256, 2)
void attn_hmma_kernel(const int* __restrict__ mask, float* __restrict__ out)
{
    extern __shared__ char smc[];
    const uint32_t smbase = smem_u32(smc);
    const int tid = threadIdx.x;
    const int w = tid >> 5, lane = tid & 31;
    const int g = lane >> 2, t = lane & 3;
    const int qt = blockIdx.x, h = blockIdx.y, b = blockIdx.z;
    const int bh = b * H_ + h;
    const int q0 = qt * BQ;
    const int qrow0 = q0 + w * 16;

    const __half* Kh = g_Kh + (size_t)bh * S_ * 64;
    const __half* Kl = g_Kl + (size_t)bh * S_ * 64;
    const __half* Vh = g_Vh + (size_t)bh * S_ * 64;
    const __half* Vl = g_Vl + (size_t)bh * S_ * 64;
    const int*    mg = mask + ((size_t)bh * S_ + q0) * S_;

    // ---- Q fragments from gmem (one-time): aQ[kc][0..3] ----
    uint32_t aQ[4][4];
    {
        const __half* Qh = g_Qh + ((size_t)bh * S_ + qrow0) * 64;
        #pragma unroll
        for (int kc = 0; kc < 4; kc++){
            int c0 = kc * 16 + 2 * t;
            aQ[kc][0] = *(const uint32_t*)(Qh + g * 64 + c0);
            aQ[kc][1] = *(const uint32_t*)(Qh + (g + 8) * 64 + c0);
            aQ[kc][2] = *(const uint32_t*)(Qh + g * 64 + c0 + 8);
            aQ[kc][3] = *(const uint32_t*)(Qh + (g + 8) * 64 + c0 + 8);
        }
    }

    float o[8][4];
    #pragma unroll
    for (int i = 0; i < 8; i++)
        #pragma unroll
        for (int j = 0; j < 4; j++) o[i][j] = 0.f;
    float lsum0 = 0.f, lsum1 = 0.f;

    // ldmatrix lane address components
    const int krow_l = (lane & 7) + ((lane >> 4) << 3);
    const uint32_t kcol_l = ((lane >> 3) & 1) * 16;
    const int vrow_l = (lane & 7) + (((lane >> 3) & 1) << 3);
    const uint32_t vcol_l = (lane >> 4) * 16;

    issue_tile(smbase, 0, Kh, Kl, Vh, Vl, 0, tid);
    issue_mask(smbase, mg, tid);

    const int* msm = (const int*)(smc + MASKB);

    for (int tt = 0; tt < NTILE; tt++){
        const int k0 = tt * BK;
        const int st = tt & 1;

        cp_wait<0>();
        __syncthreads();                 // KV(t) + mask(t) visible to all

        // ---- compress this tile's mask for this thread into 32 bits ----
        // bit layout: c*8 + rh*4 + {A.x,A.y,B.x,B.y}
        uint32_t mbits = 0;
        #pragma unroll
        for (int c = 0; c < 4; c++){
            #pragma unroll
            for (int rh = 0; rh < 2; rh++){
                int row = w * 16 + g + rh * 8;
                int cA = 4 * c + (t >> 1);
                int cB = cA + 2;
                int2 A  = *(const int2*)(msm + row * 64 + ((cA ^ g) << 2) + (t & 1) * 2);
                int2 Bv = *(const int2*)(msm + row * 64 + ((cB ^ g) << 2) + (t & 1) * 2);
                uint32_t sh = c * 8 + rh * 4;
                mbits |= (A.x  ? 1u : 0u) << sh;
                mbits |= (A.y  ? 1u : 0u) << (sh + 1);
                mbits |= (Bv.x ? 1u : 0u) << (sh + 2);
                mbits |= (Bv.y ? 1u : 0u) << (sh + 3);
            }
        }
        __syncthreads();                 // all warps done reading mask smem

        if (tt + 1 < NTILE){
            issue_tile(smbase, (tt + 1) & 1, Kh, Kl, Vh, Vl, k0 + BK, tid);
            issue_mask(smbase, mg + (k0 + BK), tid);
        }

        const uint32_t kbh = smbase + st * STAGEB;
        const uint32_t kbl = kbh + TILEB;
        const uint32_t vbh = kbh + 2 * TILEB;
        const uint32_t vbl = kbh + 3 * TILEB;

        #pragma unroll
        for (int c = 0; c < 4; c++){
            // ---- QK, fp16 2-product: S = Qh@Kh + Qh@Kl (4 indep chains) ----
            float sA0[4] = {0.f, 0.f, 0.f, 0.f};
            float sA1[4] = {0.f, 0.f, 0.f, 0.f};
            float sB0[4] = {0.f, 0.f, 0.f, 0.f};
            float sB1[4] = {0.f, 0.f, 0.f, 0.f};
            const uint32_t ka_h = kbh + (uint32_t)(c * 16 + krow_l) * 144 + kcol_l;
            const uint32_t ka_l = kbl + (uint32_t)(c * 16 + krow_l) * 144 + kcol_l;
            #pragma unroll
            for (int kc = 0; kc < 4; kc++){
                uint32_t bhf[4], blf[4];
                ldsm4(bhf, ka_h + kc * 32);
                ldsm4(blf, ka_l + kc * 32);
                hmma(sA0, aQ[kc], bhf[0], bhf[1]);
                hmma(sA1, aQ[kc], bhf[2], bhf[3]);
                hmma(sB0, aQ[kc], blf[0], blf[1]);
                hmma(sB1, aQ[kc], blf[2], blf[3]);
            }

            // ---- mask bits + exp (masked -> p = 1.0, faithful to exp(1e-20)) ----
            const uint32_t mb = mbits >> (c * 8);
            float p00 = (mb & 1u)   ? __expf(sA0[0] + sB0[0]) : 1.f;
            float p01 = (mb & 2u)   ? __expf(sA0[1] + sB0[1]) : 1.f;
            float p02 = (mb & 16u)  ? __expf(sA0[2] + sB0[2]) : 1.f;
            float p03 = (mb & 32u)  ? __expf(sA0[3] + sB0[3]) : 1.f;
            float p10 = (mb & 4u)   ? __expf(sA1[0] + sB1[0]) : 1.f;
            float p11 = (mb & 8u)   ? __expf(sA1[1] + sB1[1]) : 1.f;
            float p12 = (mb & 64u)  ? __expf(sA1[2] + sB1[2]) : 1.f;
            float p13 = (mb & 128u) ? __expf(sA1[3] + sB1[3]) : 1.f;
            lsum0 += (p00 + p01) + (p10 + p11);
            lsum1 += (p02 + p03) + (p12 + p13);

            // ---- P -> fp16 A-fragments ----
            uint32_t ph[4];
            { __half2 x = __floats2half2_rn(p00, p01); ph[0] = *(uint32_t*)&x; }
            { __half2 x = __floats2half2_rn(p02, p03); ph[1] = *(uint32_t*)&x; }
            { __half2 x = __floats2half2_rn(p10, p11); ph[2] = *(uint32_t*)&x; }
            { __half2 x = __floats2half2_rn(p12, p13); ph[3] = *(uint32_t*)&x; }

            // ---- PV, fp16 2-product: O += Ph@Vh + Ph@Vl (8 chains, depth 2) ----
            const uint32_t va_h = vbh + (uint32_t)(c * 16 + vrow_l) * 144 + vcol_l;
            const uint32_t va_l = vbl + (uint32_t)(c * 16 + vrow_l) * 144 + vcol_l;
            #pragma unroll
            for (int dt2 = 0; dt2 < 4; dt2++){
                uint32_t bhf[4], blf[4];
                ldsm4t(bhf, va_h + dt2 * 32);
                ldsm4t(blf, va_l + dt2 * 32);
                hmma(o[2 * dt2],     ph, bhf[0], bhf[1]);
                hmma(o[2 * dt2 + 1], ph, bhf[2], bhf[3]);
                hmma(o[2 * dt2],     ph, blf[0], blf[1]);
                hmma(o[2 * dt2 + 1], ph, blf[2], blf[3]);
            }
        }
    }

    // ---- row-sum reduce over the 4 lanes of each row group ----
    lsum0 += __shfl_xor_sync(0xffffffffu, lsum0, 1);
    lsum0 += __shfl_xor_sync(0xffffffffu, lsum0, 2);
    lsum1 += __shfl_xor_sync(0xffffffffu, lsum1, 1);
    lsum1 += __shfl_xor_sync(0xffffffffu, lsum1, 2);
    const float inv0 = 1.0f / lsum0;
    const float inv1 = 1.0f / lsum1;

    // ---- store O: out[b][q][h][d] ----
    float* o0 = out + (((size_t)b * S_ + qrow0 + g) * H_ + h) * D_;
    float* o8 = out + (((size_t)b * S_ + qrow0 + g + 8) * H_ + h) * D_;
    #pragma unroll
    for (int dt = 0; dt < 8; dt++){
        int col = dt * 8 + 2 * t;
        float2 r0 = make_float2(o[dt][0] * inv0, o[dt][1] * inv0);
        float2 r1 = make_float2(o[dt][2] * inv1, o[dt][3] * inv1);
        *(float2*)(o0 + col) = r0;
        *(float2*)(o8 + col) = r1;
    }
}

extern "C" void kernel_launch(void* const* d_in, const int* in_sizes, int n_in,
                              void* d_out, int out_size)
{
    const float* q    = (const float*)d_in[0];
    const float* k    = (const float*)d_in[1];
    const float* v    = (const float*)d_in[2];
    const int*   mask = (const int*)d_in[3];
    float*       out  = (float*)d_out;

    cvt_kernel<<<(3 * N4 + 255) / 256, 256>>>((const float4*)q, (const float4*)k,
                                              (const float4*)v);

    cudaFuncSetAttribute(attn_hmma_kernel,
                         cudaFuncAttributeMaxDynamicSharedMemorySize, SMEMB);
    dim3 grid(S_ / BQ, H_, B_);
    attn_hmma_kernel<<<grid, 256, SMEMB>>>(mask, out);
}

// round 9
// speedup vs baseline: 4.0893x; 1.1665x over previous
#include <cuda_runtime.h>
#include <cuda_fp16.h>
#include <cstdint>
#include <math.h>

#define B_ 4
#define S_ 2048
#define H_ 16
#define D_ 64
#define BQ 128
#define BK 64
#define NTILE (S_/BK)            // 32
#define NELEM (B_*H_*S_*D_)      // 8388608
#define N4 (NELEM/4)             // 2097152

// Pre-converted fp16 operands, head-major [b][h][s][d]
__device__ __half g_Qh[NELEM];
__device__ __half g_Kh[NELEM];
__device__ __half g_Kl[NELEM];
__device__ __half g_Vh[NELEM];

// ---------------- conversion / layout pre-pass ----------------
__global__ void cvt_kernel(const float4* __restrict__ q,
                           const float4* __restrict__ k,
                           const float4* __restrict__ v)
{
    int j = blockIdx.x * blockDim.x + threadIdx.x;
    if (j >= 3 * N4) return;
    int tsel = j / N4;
    int i = j - tsel * N4;

    const float4* src = (tsel == 0) ? q : (tsel == 1) ? k : v;
    __half* dh = (tsel == 0) ? g_Qh : (tsel == 1) ? g_Kh : g_Vh;
    const float scale = (tsel == 0) ? 0.125f : 1.0f;

    // src linear float4 index i over [b][s][h][c4]
    int c4 = i & 15, h = (i >> 4) & 15, s = (i >> 8) & 2047, b = i >> 19;
    float4 x = src[i];
    x.x *= scale; x.y *= scale; x.z *= scale; x.w *= scale;

    __half2 h01 = __floats2half2_rn(x.x, x.y);
    __half2 h23 = __floats2half2_rn(x.z, x.w);

    size_t p = ((size_t)(b * 16 + h) * 2048 + s) * 64 + c4 * 4;
    *(__half2*)(dh + p)     = h01;
    *(__half2*)(dh + p + 2) = h23;

    if (tsel == 1){   // K keeps an error-compensation (lo) plane
        __half2 l01 = __floats2half2_rn(x.x - __half2float(h01.x),
                                        x.y - __half2float(h01.y));
        __half2 l23 = __floats2half2_rn(x.z - __half2float(h23.x),
                                        x.w - __half2float(h23.y));
        *(__half2*)(g_Kl + p)     = l01;
        *(__half2*)(g_Kl + p + 2) = l23;
    }
}

// ---------------- mma / ldmatrix / cp.async primitives ----------------
__device__ __forceinline__ void hmma(float* c, const uint32_t* a, uint32_t b0, uint32_t b1){
    asm("mma.sync.aligned.m16n8k16.row.col.f32.f16.f16.f32 "
        "{%0,%1,%2,%3}, {%4,%5,%6,%7}, {%8,%9}, {%0,%1,%2,%3};"
        : "+f"(c[0]), "+f"(c[1]), "+f"(c[2]), "+f"(c[3])
        : "r"(a[0]), "r"(a[1]), "r"(a[2]), "r"(a[3]), "r"(b0), "r"(b1));
}
__device__ __forceinline__ void ldsm4(uint32_t* r, uint32_t a){
    asm volatile("ldmatrix.sync.aligned.m8n8.x4.shared.b16 {%0,%1,%2,%3}, [%4];"
        : "=r"(r[0]), "=r"(r[1]), "=r"(r[2]), "=r"(r[3]) : "r"(a));
}
__device__ __forceinline__ void ldsm4t(uint32_t* r, uint32_t a){
    asm volatile("ldmatrix.sync.aligned.m8n8.x4.trans.shared.b16 {%0,%1,%2,%3}, [%4];"
        : "=r"(r[0]), "=r"(r[1]), "=r"(r[2]), "=r"(r[3]) : "r"(a));
}
__device__ __forceinline__ void cp16(uint32_t dst, const void* src){
    asm volatile("cp.async.cg.shared.global [%0], [%1], 16;" :: "r"(dst), "l"(src));
}
__device__ __forceinline__ void cp_commit(){ asm volatile("cp.async.commit_group;"); }
template<int N> __device__ __forceinline__ void cp_wait(){
    asm volatile("cp.async.wait_group %0;" :: "n"(N));
}
__device__ __forceinline__ uint32_t smem_u32(const void* p){
    uint32_t a;
    asm("{ .reg .u64 t; cvta.to.shared.u64 t, %1; cvt.u32.u64 %0, t; }" : "=r"(a) : "l"(p));
    return a;
}

// smem: 2 stages x 3 KV tiles (Kh,Kl,Vh), each 64 rows x 144B, then mask tile
#define TILEB   9216
#define STAGEB  27648
#define MASKB   (2*STAGEB)           // 55296
#define SMEMB   (MASKB + 32768)      // 88064 per CTA; 2 CTAs/SM = 176128

__device__ __forceinline__ void issue_tile(uint32_t smbase, int st,
    const __half* Kh, const __half* Kl, const __half* Vh, int k0, int tid)
{
    const char* srcs[3] = {
        (const char*)(Kh + (size_t)k0 * 64), (const char*)(Kl + (size_t)k0 * 64),
        (const char*)(Vh + (size_t)k0 * 64) };
    uint32_t dst0 = smbase + st * STAGEB;
    #pragma unroll
    for (int i = 0; i < 6; i++){
        int sub = i >> 1;
        int c   = ((i & 1) << 8) + tid;   // 0..511 chunk within sub-tile
        int r   = c >> 3, o = c & 7;
        cp16(dst0 + sub * TILEB + r * 144 + o * 16, srcs[sub] + r * 128 + o * 16);
    }
    cp_commit();
}

// mask tile: 128 rows x 64 ints, row stride 256B, 16B chunks XOR-swizzled by row&7
__device__ __forceinline__ void issue_mask(uint32_t smbase, const int* mg, int tid)
{
    #pragma unroll
    for (int i = 0; i < 8; i++){
        int cl  = tid + i * 256;          // 0..2047
        int row = cl >> 4, cc = cl & 15;
        uint32_t dst = smbase + MASKB + row * 256 + (uint32_t)((cc ^ (row & 7)) << 4);
        cp16(dst, (const char*)(mg + (size_t)row * S_ + cc * 4));
    }
    cp_commit();
}

// ---------------- main flash-attention kernel ----------------
__global__ __launch_bounds__(256, 2)
void attn_hmma_kernel(const int* __restrict__ mask, float* __restrict__ out)
{
    extern __shared__ char smc[];
    const uint32_t smbase = smem_u32(smc);
    const int tid = threadIdx.x;
    const int w = tid >> 5, lane = tid & 31;
    const int g = lane >> 2, t = lane & 3;
    const int qt = blockIdx.x, h = blockIdx.y, b = blockIdx.z;
    const int bh = b * H_ + h;
    const int q0 = qt * BQ;
    const int qrow0 = q0 + w * 16;

    const __half* Kh = g_Kh + (size_t)bh * S_ * 64;
    const __half* Kl = g_Kl + (size_t)bh * S_ * 64;
    const __half* Vh = g_Vh + (size_t)bh * S_ * 64;
    const int*    mg = mask + ((size_t)bh * S_ + q0) * S_;

    // ---- Q fragments from gmem (one-time): aQ[kc][0..3] ----
    uint32_t aQ[4][4];
    {
        const __half* Qh = g_Qh + ((size_t)bh * S_ + qrow0) * 64;
        #pragma unroll
        for (int kc = 0; kc < 4; kc++){
            int c0 = kc * 16 + 2 * t;
            aQ[kc][0] = *(const uint32_t*)(Qh + g * 64 + c0);
            aQ[kc][1] = *(const uint32_t*)(Qh + (g + 8) * 64 + c0);
            aQ[kc][2] = *(const uint32_t*)(Qh + g * 64 + c0 + 8);
            aQ[kc][3] = *(const uint32_t*)(Qh + (g + 8) * 64 + c0 + 8);
        }
    }

    float o[8][4];
    #pragma unroll
    for (int i = 0; i < 8; i++)
        #pragma unroll
        for (int j = 0; j < 4; j++) o[i][j] = 0.f;
    float lsum0 = 0.f, lsum1 = 0.f;

    // ldmatrix lane address components
    const int krow_l = (lane & 7) + ((lane >> 4) << 3);
    const uint32_t kcol_l = ((lane >> 3) & 1) * 16;
    const int vrow_l = (lane & 7) + (((lane >> 3) & 1) << 3);
    const uint32_t vcol_l = (lane >> 4) * 16;

    issue_tile(smbase, 0, Kh, Kl, Vh, 0, tid);
    issue_mask(smbase, mg, tid);

    const int* msm = (const int*)(smc + MASKB);

    for (int tt = 0; tt < NTILE; tt++){
        const int k0 = tt * BK;
        const int st = tt & 1;

        cp_wait<0>();
        __syncthreads();                 // KV(t) + mask(t) visible to all

        // ---- compress this tile's mask for this thread into 32 bits ----
        // bit layout: c*8 + rh*4 + {A.x,A.y,B.x,B.y}
        uint32_t mbits = 0;
        #pragma unroll
        for (int c = 0; c < 4; c++){
            #pragma unroll
            for (int rh = 0; rh < 2; rh++){
                int row = w * 16 + g + rh * 8;
                int cA = 4 * c + (t >> 1);
                int cB = cA + 2;
                int2 A  = *(const int2*)(msm + row * 64 + ((cA ^ g) << 2) + (t & 1) * 2);
                int2 Bv = *(const int2*)(msm + row * 64 + ((cB ^ g) << 2) + (t & 1) * 2);
                uint32_t sh = c * 8 + rh * 4;
                mbits |= (A.x  ? 1u : 0u) << sh;
                mbits |= (A.y  ? 1u : 0u) << (sh + 1);
                mbits |= (Bv.x ? 1u : 0u) << (sh + 2);
                mbits |= (Bv.y ? 1u : 0u) << (sh + 3);
            }
        }
        __syncthreads();                 // all warps done reading mask smem

        if (tt + 1 < NTILE){
            issue_tile(smbase, (tt + 1) & 1, Kh, Kl, Vh, k0 + BK, tid);
            issue_mask(smbase, mg + (k0 + BK), tid);
        }

        const uint32_t kbh = smbase + st * STAGEB;
        const uint32_t kbl = kbh + TILEB;
        const uint32_t vbh = kbh + 2 * TILEB;

        #pragma unroll
        for (int c = 0; c < 4; c++){
            // ---- QK, fp16 2-product: S = Qh@Kh + Qh@Kl (4 indep chains) ----
            float sA0[4] = {0.f, 0.f, 0.f, 0.f};
            float sA1[4] = {0.f, 0.f, 0.f, 0.f};
            float sB0[4] = {0.f, 0.f, 0.f, 0.f};
            float sB1[4] = {0.f, 0.f, 0.f, 0.f};
            const uint32_t ka_h = kbh + (uint32_t)(c * 16 + krow_l) * 144 + kcol_l;
            const uint32_t ka_l = kbl + (uint32_t)(c * 16 + krow_l) * 144 + kcol_l;
            #pragma unroll
            for (int kc = 0; kc < 4; kc++){
                uint32_t bhf[4], blf[4];
                ldsm4(bhf, ka_h + kc * 32);
                ldsm4(blf, ka_l + kc * 32);
                hmma(sA0, aQ[kc], bhf[0], bhf[1]);
                hmma(sA1, aQ[kc], bhf[2], bhf[3]);
                hmma(sB0, aQ[kc], blf[0], blf[1]);
                hmma(sB1, aQ[kc], blf[2], blf[3]);
            }

            // ---- mask bits + exp (masked -> p = 1.0, faithful to exp(1e-20)) ----
            const uint32_t mb = mbits >> (c * 8);
            float p00 = (mb & 1u)   ? __expf(sA0[0] + sB0[0]) : 1.f;
            float p01 = (mb & 2u)   ? __expf(sA0[1] + sB0[1]) : 1.f;
            float p02 = (mb & 16u)  ? __expf(sA0[2] + sB0[2]) : 1.f;
            float p03 = (mb & 32u)  ? __expf(sA0[3] + sB0[3]) : 1.f;
            float p10 = (mb & 4u)   ? __expf(sA1[0] + sB1[0]) : 1.f;
            float p11 = (mb & 8u)   ? __expf(sA1[1] + sB1[1]) : 1.f;
            float p12 = (mb & 64u)  ? __expf(sA1[2] + sB1[2]) : 1.f;
            float p13 = (mb & 128u) ? __expf(sA1[3] + sB1[3]) : 1.f;
            lsum0 += (p00 + p01) + (p10 + p11);
            lsum1 += (p02 + p03) + (p12 + p13);

            // ---- P -> fp16 A-fragments ----
            uint32_t ph[4];
            { __half2 x = __floats2half2_rn(p00, p01); ph[0] = *(uint32_t*)&x; }
            { __half2 x = __floats2half2_rn(p02, p03); ph[1] = *(uint32_t*)&x; }
            { __half2 x = __floats2half2_rn(p10, p11); ph[2] = *(uint32_t*)&x; }
            { __half2 x = __floats2half2_rn(p12, p13); ph[3] = *(uint32_t*)&x; }

            // ---- PV, single product: O += Ph@Vh (8 indep chains, depth 1) ----
            const uint32_t va_h = vbh + (uint32_t)(c * 16 + vrow_l) * 144 + vcol_l;
            #pragma unroll
            for (int dt2 = 0; dt2 < 4; dt2++){
                uint32_t bhf[4];
                ldsm4t(bhf, va_h + dt2 * 32);
                hmma(o[2 * dt2],     ph, bhf[0], bhf[1]);
                hmma(o[2 * dt2 + 1], ph, bhf[2], bhf[3]);
            }
        }
    }

    // ---- row-sum reduce over the 4 lanes of each row group ----
    lsum0 += __shfl_xor_sync(0xffffffffu, lsum0, 1);
    lsum0 += __shfl_xor_sync(0xffffffffu, lsum0, 2);
    lsum1 += __shfl_xor_sync(0xffffffffu, lsum1, 1);
    lsum1 += __shfl_xor_sync(0xffffffffu, lsum1, 2);
    const float inv0 = 1.0f / lsum0;
    const float inv1 = 1.0f / lsum1;

    // ---- store O: out[b][q][h][d] ----
    float* o0 = out + (((size_t)b * S_ + qrow0 + g) * H_ + h) * D_;
    float* o8 = out + (((size_t)b * S_ + qrow0 + g + 8) * H_ + h) * D_;
    #pragma unroll
    for (int dt = 0; dt < 8; dt++){
        int col = dt * 8 + 2 * t;
        float2 r0 = make_float2(o[dt][0] * inv0, o[dt][1] * inv0);
        float2 r1 = make_float2(o[dt][2] * inv1, o[dt][3] * inv1);
        *(float2*)(o0 + col) = r0;
        *(float2*)(o8 + col) = r1;
    }
}

extern "C" void kernel_launch(void* const* d_in, const int* in_sizes, int n_in,
                              void* d_out, int out_size)
{
    const float* q    = (const float*)d_in[0];
    const float* k    = (const float*)d_in[1];
    const float* v    = (const float*)d_in[2];
    const int*   mask = (const int*)d_in[3];
    float*       out  = (float*)d_out;

    cvt_kernel<<<(3 * N4 + 255) / 256, 256>>>((const float4*)q, (const float4*)k,
                                              (const float4*)v);

    cudaFuncSetAttribute(attn_hmma_kernel,
                         cudaFuncAttributeMaxDynamicSharedMemorySize, SMEMB);
    dim3 grid(S_ / BQ, H_, B_);
    attn_hmma_kernel<<<grid, 256, SMEMB>>>(mask, out);
}

// round 10
// speedup vs baseline: 6.2304x; 1.5236x over previous
#include <cuda_runtime.h>
#include <cuda_fp16.h>
#include <cstdint>
#include <math.h>

#define B_ 4
#define S_ 2048
#define H_ 16
#define D_ 64
#define BQ 128
#define BK 64
#define NTILE (S_/BK)            // 32
#define NELEM (B_*H_*S_*D_)      // 8388608
#define N4 (NELEM/4)             // 2097152

// Pre-converted fp16 operands, head-major [b][h][s][d]
__device__ __half g_Qh[NELEM];
__device__ __half g_Kh[NELEM];
__device__ __half g_Vh[NELEM];

// ---------------- conversion / layout pre-pass ----------------
// Q is scaled by (1/8)*log2(e): scores come out in the log2 domain, so
// softmax is a single ex2 and masked->0 gives p = 2^0 = 1 exactly.
__global__ void cvt_kernel(const float4* __restrict__ q,
                           const float4* __restrict__ k,
                           const float4* __restrict__ v)
{
    int j = blockIdx.x * blockDim.x + threadIdx.x;
    if (j >= 3 * N4) return;
    int tsel = j / N4;
    int i = j - tsel * N4;

    const float4* src = (tsel == 0) ? q : (tsel == 1) ? k : v;
    __half* dh = (tsel == 0) ? g_Qh : (tsel == 1) ? g_Kh : g_Vh;
    const float scale = (tsel == 0) ? 0.18033688f : 1.0f;  // 0.125*log2(e)

    // src linear float4 index i over [b][s][h][c4]
    int c4 = i & 15, h = (i >> 4) & 15, s = (i >> 8) & 2047, b = i >> 19;
    float4 x = src[i];
    x.x *= scale; x.y *= scale; x.z *= scale; x.w *= scale;

    __half2 h01 = __floats2half2_rn(x.x, x.y);
    __half2 h23 = __floats2half2_rn(x.z, x.w);

    size_t p = ((size_t)(b * 16 + h) * 2048 + s) * 64 + c4 * 4;
    *(__half2*)(dh + p)     = h01;
    *(__half2*)(dh + p + 2) = h23;
}

// ---------------- mma / ldmatrix / cp.async primitives ----------------
__device__ __forceinline__ void hmma(float* c, const uint32_t* a, uint32_t b0, uint32_t b1){
    asm("mma.sync.aligned.m16n8k16.row.col.f32.f16.f16.f32 "
        "{%0,%1,%2,%3}, {%4,%5,%6,%7}, {%8,%9}, {%0,%1,%2,%3};"
        : "+f"(c[0]), "+f"(c[1]), "+f"(c[2]), "+f"(c[3])
        : "r"(a[0]), "r"(a[1]), "r"(a[2]), "r"(a[3]), "r"(b0), "r"(b1));
}
__device__ __forceinline__ void ldsm4(uint32_t* r, uint32_t a){
    asm volatile("ldmatrix.sync.aligned.m8n8.x4.shared.b16 {%0,%1,%2,%3}, [%4];"
        : "=r"(r[0]), "=r"(r[1]), "=r"(r[2]), "=r"(r[3]) : "r"(a));
}
__device__ __forceinline__ void ldsm4t(uint32_t* r, uint32_t a){
    asm volatile("ldmatrix.sync.aligned.m8n8.x4.trans.shared.b16 {%0,%1,%2,%3}, [%4];"
        : "=r"(r[0]), "=r"(r[1]), "=r"(r[2]), "=r"(r[3]) : "r"(a));
}
__device__ __forceinline__ void cp16(uint32_t dst, const void* src){
    asm volatile("cp.async.cg.shared.global [%0], [%1], 16;" :: "r"(dst), "l"(src));
}
__device__ __forceinline__ void cp_commit(){ asm volatile("cp.async.commit_group;"); }
template<int N> __device__ __forceinline__ void cp_wait(){
    asm volatile("cp.async.wait_group %0;" :: "n"(N));
}
__device__ __forceinline__ uint32_t smem_u32(const void* p){
    uint32_t a;
    asm("{ .reg .u64 t; cvta.to.shared.u64 t, %1; cvt.u32.u64 %0, t; }" : "=r"(a) : "l"(p));
    return a;
}
// pack (lo,hi) floats -> f16x2 (first PTX src is the HIGH half)
__device__ __forceinline__ uint32_t f2h2(float lo, float hi){
    uint32_t r; asm("cvt.rn.f16x2.f32 %0, %1, %2;" : "=r"(r) : "f"(hi), "f"(lo)); return r;
}
__device__ __forceinline__ uint32_t ex2h2(uint32_t x){
    uint32_t r; asm("ex2.approx.f16x2 %0, %1;" : "=r"(r) : "r"(x)); return r;
}

// smem: 2 stages x 2 KV tiles (Kh,Vh), each 64 rows x 144B; 2 mask buffers
#define TILEB   9216
#define STAGEB  (2*TILEB)            // 18432
#define MASK0   (2*STAGEB)           // 36864
#define MASKBUF 32768
#define SMEMB   (MASK0 + 2*MASKBUF)  // 102400 per CTA; 2 CTAs/SM = 204800

__device__ __forceinline__ void issue_tile(uint32_t smbase, int st,
    const __half* Kh, const __half* Vh, int k0, int tid)
{
    const char* srcs[2] = {
        (const char*)(Kh + (size_t)k0 * 64), (const char*)(Vh + (size_t)k0 * 64) };
    uint32_t dst0 = smbase + st * STAGEB;
    #pragma unroll
    for (int i = 0; i < 4; i++){
        int sub = i >> 1;
        int c   = ((i & 1) << 8) + tid;   // 0..511 chunk within sub-tile
        int r   = c >> 3, o = c & 7;
        cp16(dst0 + sub * TILEB + r * 144 + o * 16, srcs[sub] + r * 128 + o * 16);
    }
    cp_commit();
}

// mask tile: 128 rows x 64 ints, row stride 256B, 16B chunks XOR-swizzled by row&7
__device__ __forceinline__ void issue_mask(uint32_t smbase, int mb_st,
                                           const int* mg, int tid)
{
    uint32_t base = smbase + MASK0 + (uint32_t)mb_st * MASKBUF;
    #pragma unroll
    for (int i = 0; i < 8; i++){
        int cl  = tid + i * 256;          // 0..2047
        int row = cl >> 4, cc = cl & 15;
        uint32_t dst = base + row * 256 + (uint32_t)((cc ^ (row & 7)) << 4);
        cp16(dst, (const char*)(mg + (size_t)row * S_ + cc * 4));
    }
    cp_commit();
}

// ---------------- main flash-attention kernel ----------------
__global__ __launch_bounds__(256, 2)
void attn_hmma_kernel(const int* __restrict__ mask, float* __restrict__ out)
{
    extern __shared__ char smc[];
    const uint32_t smbase = smem_u32(smc);
    const int tid = threadIdx.x;
    const int w = tid >> 5, lane = tid & 31;
    const int g = lane >> 2, t = lane & 3;
    const int qt = blockIdx.x, h = blockIdx.y, b = blockIdx.z;
    const int bh = b * H_ + h;
    const int q0 = qt * BQ;
    const int qrow0 = q0 + w * 16;

    const __half* Kh = g_Kh + (size_t)bh * S_ * 64;
    const __half* Vh = g_Vh + (size_t)bh * S_ * 64;
    const int*    mg = mask + ((size_t)bh * S_ + q0) * S_;

    // ---- Q fragments from gmem (one-time): aQ[kc][0..3] ----
    uint32_t aQ[4][4];
    {
        const __half* Qh = g_Qh + ((size_t)bh * S_ + qrow0) * 64;
        #pragma unroll
        for (int kc = 0; kc < 4; kc++){
            int c0 = kc * 16 + 2 * t;
            aQ[kc][0] = *(const uint32_t*)(Qh + g * 64 + c0);
            aQ[kc][1] = *(const uint32_t*)(Qh + (g + 8) * 64 + c0);
            aQ[kc][2] = *(const uint32_t*)(Qh + g * 64 + c0 + 8);
            aQ[kc][3] = *(const uint32_t*)(Qh + (g + 8) * 64 + c0 + 8);
        }
    }

    float o[8][4];
    #pragma unroll
    for (int i = 0; i < 8; i++)
        #pragma unroll
        for (int j = 0; j < 4; j++) o[i][j] = 0.f;
    float lacc[4] = {0.f, 0.f, 0.f, 0.f};     // ones-column: row sums
    const uint32_t bone = (lane < 4) ? 0x3C003C00u : 0u;  // B[k][0]=1.0

    // ldmatrix lane address components
    const int krow_l = (lane & 7) + ((lane >> 4) << 3);
    const uint32_t kcol_l = ((lane >> 3) & 1) * 16;
    const int vrow_l = (lane & 7) + (((lane >> 3) & 1) << 3);
    const uint32_t vcol_l = (lane >> 4) * 16;

    issue_tile(smbase, 0, Kh, Vh, 0, tid);
    issue_mask(smbase, 0, mg, tid);

    for (int tt = 0; tt < NTILE; tt++){
        const int k0 = tt * BK;
        const int st = tt & 1;

        cp_wait<0>();
        __syncthreads();                 // KV(t) + mask(t) visible to all

        if (tt + 1 < NTILE){
            issue_tile(smbase, st ^ 1, Kh, Vh, k0 + BK, tid);
            issue_mask(smbase, st ^ 1, mg + (k0 + BK), tid);
        }

        // ---- compress this tile's mask for this thread into 32 bits ----
        // bit layout: c*8 + rh*4 + {A.x,A.y,B.x,B.y}
        const int* msm = (const int*)(smc + MASK0 + st * MASKBUF);
        uint32_t mbits = 0;
        #pragma unroll
        for (int c = 0; c < 4; c++){
            #pragma unroll
            for (int rh = 0; rh < 2; rh++){
                int row = w * 16 + g + rh * 8;
                int cA = 4 * c + (t >> 1);
                int cB = cA + 2;
                int2 A  = *(const int2*)(msm + row * 64 + ((cA ^ g) << 2) + (t & 1) * 2);
                int2 Bv = *(const int2*)(msm + row * 64 + ((cB ^ g) << 2) + (t & 1) * 2);
                uint32_t sh = c * 8 + rh * 4;
                mbits |= (A.x  ? 1u : 0u) << sh;
                mbits |= (A.y  ? 1u : 0u) << (sh + 1);
                mbits |= (Bv.x ? 1u : 0u) << (sh + 2);
                mbits |= (Bv.y ? 1u : 0u) << (sh + 3);
            }
        }

        const uint32_t kbh = smbase + st * STAGEB;
        const uint32_t vbh = kbh + TILEB;

        #pragma unroll
        for (int c = 0; c < 4; c++){
            // ---- QK, plain fp16: S = Qh@Kh (2 indep chains, depth 4) ----
            float sA0[4] = {0.f, 0.f, 0.f, 0.f};
            float sA1[4] = {0.f, 0.f, 0.f, 0.f};
            const uint32_t ka_h = kbh + (uint32_t)(c * 16 + krow_l) * 144 + kcol_l;
            #pragma unroll
            for (int kc = 0; kc < 4; kc++){
                uint32_t bhf[4];
                ldsm4(bhf, ka_h + kc * 32);
                hmma(sA0, aQ[kc], bhf[0], bhf[1]);
                hmma(sA1, aQ[kc], bhf[2], bhf[3]);
            }

            // ---- softmax in log2 domain: masked->0 (p=2^0=1), ex2.f16x2 ----
            const uint32_t mb = mbits >> (c * 8);
            float s00 = (mb & 1u)   ? sA0[0] : 0.f;
            float s01 = (mb & 2u)   ? sA0[1] : 0.f;
            float s02 = (mb & 16u)  ? sA0[2] : 0.f;
            float s03 = (mb & 32u)  ? sA0[3] : 0.f;
            float s10 = (mb & 4u)   ? sA1[0] : 0.f;
            float s11 = (mb & 8u)   ? sA1[1] : 0.f;
            float s12 = (mb & 64u)  ? sA1[2] : 0.f;
            float s13 = (mb & 128u) ? sA1[3] : 0.f;

            uint32_t ph[4];
            ph[0] = ex2h2(f2h2(s00, s01));
            ph[1] = ex2h2(f2h2(s02, s03));
            ph[2] = ex2h2(f2h2(s10, s11));
            ph[3] = ex2h2(f2h2(s12, s13));

            // ---- PV: O += Ph@Vh; lsum via ones-column GEMM ----
            const uint32_t va_h = vbh + (uint32_t)(c * 16 + vrow_l) * 144 + vcol_l;
            #pragma unroll
            for (int dt2 = 0; dt2 < 4; dt2++){
                uint32_t bhf[4];
                ldsm4t(bhf, va_h + dt2 * 32);
                hmma(o[2 * dt2],     ph, bhf[0], bhf[1]);
                hmma(o[2 * dt2 + 1], ph, bhf[2], bhf[3]);
            }
            hmma(lacc, ph, bone, bone);
        }
    }

    // ---- row sums live in col 0 (threads t==0); broadcast across the quad ----
    const float lsum0 = __shfl_sync(0xffffffffu, lacc[0], lane & ~3);
    const float lsum1 = __shfl_sync(0xffffffffu, lacc[2], lane & ~3);
    const float inv0 = 1.0f / lsum0;
    const float inv1 = 1.0f / lsum1;

    // ---- store O: out[b][q][h][d] ----
    float* o0 = out + (((size_t)b * S_ + qrow0 + g) * H_ + h) * D_;
    float* o8 = out + (((size_t)b * S_ + qrow0 + g + 8) * H_ + h) * D_;
    #pragma unroll
    for (int dt = 0; dt < 8; dt++){
        int col = dt * 8 + 2 * t;
        float2 r0 = make_float2(o[dt][0] * inv0, o[dt][1] * inv0);
        float2 r1 = make_float2(o[dt][2] * inv1, o[dt][3] * inv1);
        *(float2*)(o0 + col) = r0;
        *(float2*)(o8 + col) = r1;
    }
}

extern "C" void kernel_launch(void* const* d_in, const int* in_sizes, int n_in,
                              void* d_out, int out_size)
{
    const float* q    = (const float*)d_in[0];
    const float* k    = (const float*)d_in[1];
    const float* v    = (const float*)d_in[2];
    const int*   mask = (const int*)d_in[3];
    float*       out  = (float*)d_out;

    cvt_kernel<<<(3 * N4 + 255) / 256, 256>>>((const float4*)q, (const float4*)k,
                                              (const float4*)v);

    cudaFuncSetAttribute(attn_hmma_kernel,
                         cudaFuncAttributeMaxDynamicSharedMemorySize, SMEMB);
    dim3 grid(S_ / BQ, H_, B_);
    attn_hmma_kernel<<<grid, 256, SMEMB>>>(mask, out);
}